// round 2
// baseline (speedup 1.0000x reference)
#include <cuda_runtime.h>

#define BB 256
#define TT 1024
#define DD 128
#define HH 256
#define CC 10
#define NBLK 96
#define NB0 32     // layer-0 blocks; remaining 64 are layer-1

typedef unsigned long long u64;

// ---------------- device scratch ----------------------------------------------
__device__ float g_xT [(size_t)TT * DD * BB];        // [t][d][b]
__device__ float g_xg0[(size_t)TT * HH * 4 * BB];    // [t][u][g][b]
__device__ float g_h0 [(size_t)(TT + 1) * HH * BB];  // slot t+1 = h0(t); slot0 = 0
__device__ float g_h1 [(size_t)(TT + 1) * HH * BB];  // slot t+1 = h1(t); slot0 = 0
__device__ float g_c0 [HH * BB];
__device__ float g_c1 [HH * BB];
__device__ float g_Wt_ih0[DD * HH * 4];              // [d][u][g]
__device__ float g_Wt_hh0[HH * HH * 4];              // [k][u][g]
__device__ float g_Wt_ih1[HH * HH * 4];
__device__ float g_Wt_hh1[HH * HH * 4];
__device__ unsigned g_arrive;
__device__ unsigned g_release;

// ---------------- packed fp32x2 helpers ----------------------------------------
__device__ __forceinline__ u64 dup2(float w) {
    u64 r; asm("mov.b64 %0,{%1,%1};" : "=l"(r) : "f"(w)); return r;
}
__device__ __forceinline__ void pfma(u64& d, u64 a, u64 b) {
    asm("fma.rn.f32x2 %0,%1,%2,%0;" : "+l"(d) : "l"(a), "l"(b));
}
__device__ __forceinline__ float2 unpk(u64 v) {
    float2 f; asm("mov.b64 {%0,%1},%2;" : "=f"(f.x), "=f"(f.y) : "l"(v)); return f;
}
__device__ __forceinline__ float sigm(float x) { return 1.f / (1.f + __expf(-x)); }
__device__ __forceinline__ float tanh_(float x) { return 1.f - 2.f / (__expf(2.f * x) + 1.f); }

// ---------------- init (every replay) ------------------------------------------
__global__ void init_kernel() {
    int n = HH * BB;
    for (int i = blockIdx.x * blockDim.x + threadIdx.x; i < n; i += gridDim.x * blockDim.x) {
        g_c0[i] = 0.f; g_c1[i] = 0.f;
        g_h0[i] = 0.f; g_h1[i] = 0.f;   // slot 0 of each sequence
    }
    if (blockIdx.x == 0 && threadIdx.x == 0) { g_arrive = 0u; g_release = 0u; }
}

// ---------------- x transpose: xT[t][d][b] = x[b][t][d] -------------------------
__global__ __launch_bounds__(256) void transpose_x(const float* __restrict__ x) {
    __shared__ float tile[64][33];
    const int t = blockIdx.x, b0 = blockIdx.y * 64;
    for (int dc = 0; dc < DD; dc += 32) {
        for (int i = threadIdx.x; i < 64 * 32; i += 256) {
            int bi = i >> 5, di = i & 31;
            tile[bi][di] = x[((size_t)(b0 + bi) * TT + t) * DD + dc + di];
        }
        __syncthreads();
        for (int i = threadIdx.x; i < 64 * 32; i += 256) {
            int di = i >> 6, bi = i & 63;
            g_xT[((size_t)t * DD + dc + di) * BB + b0 + bi] = tile[bi][di];
        }
        __syncthreads();
    }
}

// ---------------- weight transpose: Wt[k][u][g] = W[g*HH+u][k] ------------------
__global__ void transpose_w(const float* __restrict__ Wih0, const float* __restrict__ Whh0,
                            const float* __restrict__ Wih1, const float* __restrict__ Whh1) {
    const int NI = DD * HH * 4, NH = HH * HH * 4;
    int idx = blockIdx.x * blockDim.x + threadIdx.x;
    if (idx < NI) {
        int g = idx & 3, u = (idx >> 2) & 255, k = idx >> 10;
        g_Wt_ih0[idx] = Wih0[(g * HH + u) * DD + k];
    } else if (idx < NI + 3 * NH) {
        int j = idx - NI, m = j / NH, r = j % NH;
        int g = r & 3, u = (r >> 2) & 255, k = r >> 10;
        float v;
        if (m == 0)      { v = Whh0[(g * HH + u) * HH + k]; g_Wt_hh0[r] = v; }
        else if (m == 1) { v = Wih1[(g * HH + u) * HH + k]; g_Wt_ih1[r] = v; }
        else             { v = Whh1[(g * HH + u) * HH + k]; g_Wt_hh1[r] = v; }
    }
}

// ---------------- GEMM cores (register-tiled, f32x2) ----------------------------
// acc[uu][g][p] over 8 batch (4 pairs), 2 units x 4 gates
__device__ __forceinline__ void gemm_2u(const float* __restrict__ A,   // [k][BB]
                                        const float* __restrict__ Wt,  // [k][HH][4]
                                        int K, int bofs, int u0, u64 acc[2][4][4]) {
#pragma unroll 2
    for (int k = 0; k < K; ++k) {
        ulonglong2 a0 = *(const ulonglong2*)(A + (size_t)k * BB + bofs);
        ulonglong2 a1 = *(const ulonglong2*)(A + (size_t)k * BB + bofs + 4);
        float4 w0 = *(const float4*)(Wt + ((size_t)k * HH + u0) * 4);
        float4 w1 = *(const float4*)(Wt + ((size_t)k * HH + u0 + 1) * 4);
        u64 a[4] = {a0.x, a0.y, a1.x, a1.y};
        float wv0[4] = {w0.x, w0.y, w0.z, w0.w};
        float wv1[4] = {w1.x, w1.y, w1.z, w1.w};
#pragma unroll
        for (int g = 0; g < 4; ++g) {
            u64 wp = dup2(wv0[g]);
#pragma unroll
            for (int p = 0; p < 4; ++p) pfma(acc[0][g][p], a[p], wp);
        }
#pragma unroll
        for (int g = 0; g < 4; ++g) {
            u64 wp = dup2(wv1[g]);
#pragma unroll
            for (int p = 0; p < 4; ++p) pfma(acc[1][g][p], a[p], wp);
        }
    }
}

// acc[g][p]: 1 unit x 4 gates x 8 batch
__device__ __forceinline__ void gemm_1u(const float* __restrict__ A,
                                        const float* __restrict__ Wt,
                                        int bofs, int u, u64 acc[4][4]) {
#pragma unroll 4
    for (int k = 0; k < HH; ++k) {
        ulonglong2 a0 = *(const ulonglong2*)(A + (size_t)k * BB + bofs);
        ulonglong2 a1 = *(const ulonglong2*)(A + (size_t)k * BB + bofs + 4);
        float4 w = *(const float4*)(Wt + ((size_t)k * HH + u) * 4);
        u64 a[4] = {a0.x, a0.y, a1.x, a1.y};
        float wv[4] = {w.x, w.y, w.z, w.w};
#pragma unroll
        for (int g = 0; g < 4; ++g) {
            u64 wp = dup2(wv[g]);
#pragma unroll
            for (int p = 0; p < 4; ++p) pfma(acc[g][p], a[p], wp);
        }
    }
}

// ---------------- xg0 = x @ Wih0^T + b0, layout [t][u][g][b] --------------------
__global__ __launch_bounds__(128) void xg0_kernel(const float* __restrict__ b0v) {
    const int bid = blockIdx.x;
    const int t = bid >> 5, sub = bid & 31;
    const int ub = sub >> 2, bb = sub & 3;
    const int m_t = threadIdx.x & 7, n_t = threadIdx.x >> 3;
    const int u0 = ub * 32 + n_t * 2;
    const int bofs = bb * 64 + m_t * 8;

    u64 acc[2][4][4];
#pragma unroll
    for (int uu = 0; uu < 2; ++uu)
#pragma unroll
        for (int g = 0; g < 4; ++g) {
            u64 bp = dup2(b0v[g * HH + u0 + uu]);
#pragma unroll
            for (int p = 0; p < 4; ++p) acc[uu][g][p] = bp;
        }
    gemm_2u(g_xT + (size_t)t * DD * BB, g_Wt_ih0, DD, bofs, u0, acc);

    float* X = g_xg0 + (size_t)t * HH * 4 * BB;
#pragma unroll
    for (int uu = 0; uu < 2; ++uu)
#pragma unroll
        for (int g = 0; g < 4; ++g) {
            float* dst = X + (((size_t)(u0 + uu) * 4) + g) * BB + bofs;
            ulonglong2 v0; v0.x = acc[uu][g][0]; v0.y = acc[uu][g][1];
            ulonglong2 v1; v1.x = acc[uu][g][2]; v1.y = acc[uu][g][3];
            *(ulonglong2*)dst = v0;
            *(ulonglong2*)(dst + 4) = v1;
        }
}

// ---------------- software grid barrier ----------------------------------------
__device__ __forceinline__ void grid_barrier(unsigned gen) {
    __syncthreads();
    if (threadIdx.x == 0) {
        __threadfence();
        unsigned prev = atomicAdd(&g_arrive, 1u);
        if (prev == NBLK - 1u) {
            g_arrive = 0u;
            __threadfence();
            *(volatile unsigned*)&g_release = gen;
        } else {
            while (*(volatile unsigned*)&g_release < gen) __nanosleep(64);
            __threadfence();
        }
    }
    __syncthreads();
}

// ---------------- persistent LSTM (both layers pipelined) ------------------------
__device__ __forceinline__ void l0_step(int t, int bofs, int u0) {
    u64 acc[2][4][4];
    const float* X = g_xg0 + (size_t)t * HH * 4 * BB;
#pragma unroll
    for (int uu = 0; uu < 2; ++uu)
#pragma unroll
        for (int g = 0; g < 4; ++g) {
            const float* src = X + (((size_t)(u0 + uu) * 4) + g) * BB + bofs;
            ulonglong2 v0 = *(const ulonglong2*)src;
            ulonglong2 v1 = *(const ulonglong2*)(src + 4);
            acc[uu][g][0] = v0.x; acc[uu][g][1] = v0.y;
            acc[uu][g][2] = v1.x; acc[uu][g][3] = v1.y;
        }
    gemm_2u(g_h0 + (size_t)t * HH * BB, g_Wt_hh0, HH, bofs, u0, acc);
#pragma unroll
    for (int uu = 0; uu < 2; ++uu) {
        int u = u0 + uu;
        float* crow = g_c0 + (size_t)u * BB + bofs;
        float* hrow = g_h0 + (size_t)(t + 1) * HH * BB + (size_t)u * BB + bofs;
        float hv[8];
#pragma unroll
        for (int p = 0; p < 4; ++p) {
            float2 iv = unpk(acc[uu][0][p]);
            float2 fv = unpk(acc[uu][1][p]);
            float2 gv = unpk(acc[uu][2][p]);
            float2 ov = unpk(acc[uu][3][p]);
            float ca = sigm(fv.x) * crow[p * 2]     + sigm(iv.x) * tanh_(gv.x);
            float cb = sigm(fv.y) * crow[p * 2 + 1] + sigm(iv.y) * tanh_(gv.y);
            crow[p * 2] = ca; crow[p * 2 + 1] = cb;
            hv[p * 2]     = sigm(ov.x) * tanh_(ca);
            hv[p * 2 + 1] = sigm(ov.y) * tanh_(cb);
        }
        *(float4*)hrow       = make_float4(hv[0], hv[1], hv[2], hv[3]);
        *(float4*)(hrow + 4) = make_float4(hv[4], hv[5], hv[6], hv[7]);
    }
}

__device__ __forceinline__ void l1_step(int s, int bofs, int u, const float* __restrict__ b1v) {
    u64 acc[4][4];
#pragma unroll
    for (int g = 0; g < 4; ++g) {
        u64 bp = dup2(b1v[g * HH + u]);
#pragma unroll
        for (int p = 0; p < 4; ++p) acc[g][p] = bp;
    }
    gemm_1u(g_h0 + (size_t)(s + 1) * HH * BB, g_Wt_ih1, bofs, u, acc);
    gemm_1u(g_h1 + (size_t)s * HH * BB,       g_Wt_hh1, bofs, u, acc);
    float* crow = g_c1 + (size_t)u * BB + bofs;
    float* hrow = g_h1 + (size_t)(s + 1) * HH * BB + (size_t)u * BB + bofs;
    float hv[8];
#pragma unroll
    for (int p = 0; p < 4; ++p) {
        float2 iv = unpk(acc[0][p]);
        float2 fv = unpk(acc[1][p]);
        float2 gv = unpk(acc[2][p]);
        float2 ov = unpk(acc[3][p]);
        float ca = sigm(fv.x) * crow[p * 2]     + sigm(iv.x) * tanh_(gv.x);
        float cb = sigm(fv.y) * crow[p * 2 + 1] + sigm(iv.y) * tanh_(gv.y);
        crow[p * 2] = ca; crow[p * 2 + 1] = cb;
        hv[p * 2]     = sigm(ov.x) * tanh_(ca);
        hv[p * 2 + 1] = sigm(ov.y) * tanh_(cb);
    }
    *(float4*)hrow       = make_float4(hv[0], hv[1], hv[2], hv[3]);
    *(float4*)(hrow + 4) = make_float4(hv[4], hv[5], hv[6], hv[7]);
}

__global__ __launch_bounds__(128, 1) void lstm_persist(const float* __restrict__ b1v) {
    const int tid = threadIdx.x;
    const int m_t = tid & 7, n_t = tid >> 3;
    const int blk = blockIdx.x;
    if (blk < NB0) {
        // layer 0: 8 u-tiles (32 units) x 4 b-tiles (64 batch)
        const int u0 = (blk >> 2) * 32 + n_t * 2;
        const int bofs = (blk & 3) * 64 + m_t * 8;
        for (int t = 0; t < TT; ++t) {
            l0_step(t, bofs, u0);
            grid_barrier((unsigned)(t + 1));
        }
    } else {
        // layer 1: 16 u-tiles (16 units) x 4 b-tiles (64 batch)
        const int idx = blk - NB0;
        const int u = (idx >> 2) * 16 + n_t;
        const int bofs = (idx & 3) * 64 + m_t * 8;
        for (int t = 0; t < TT; ++t) {
            if (t >= 1) l1_step(t - 1, bofs, u, b1v);
            grid_barrier((unsigned)(t + 1));
        }
        l1_step(TT - 1, bofs, u, b1v);  // tail: s = 1023
    }
}

// ---------------- dense + softmax -----------------------------------------------
__global__ __launch_bounds__(256) void dense_softmax(const float* __restrict__ Wd,
                                                     const float* __restrict__ bd,
                                                     float* __restrict__ out) {
    const int b = threadIdx.x;
    const float* h = g_h1 + (size_t)TT * HH * BB;
    float acc[CC];
#pragma unroll
    for (int c = 0; c < CC; ++c) acc[c] = bd[c];
    for (int u = 0; u < HH; ++u) {
        float hv = h[(size_t)u * BB + b];
#pragma unroll
        for (int c = 0; c < CC; ++c) acc[c] += hv * Wd[c * HH + u];
    }
    float mx = acc[0];
#pragma unroll
    for (int c = 1; c < CC; ++c) mx = fmaxf(mx, acc[c]);
    float sum = 0.f;
#pragma unroll
    for (int c = 0; c < CC; ++c) { acc[c] = expf(acc[c] - mx); sum += acc[c]; }
    float inv = 1.f / sum;
#pragma unroll
    for (int c = 0; c < CC; ++c) out[b * CC + c] = acc[c] * inv;
}

// ---------------- launch ---------------------------------------------------------
extern "C" void kernel_launch(void* const* d_in, const int* in_sizes, int n_in,
                              void* d_out, int out_size) {
    const float* x    = (const float*)d_in[0];
    const float* Wih0 = (const float*)d_in[1];
    const float* Whh0 = (const float*)d_in[2];
    const float* b0v  = (const float*)d_in[3];
    const float* Wih1 = (const float*)d_in[4];
    const float* Whh1 = (const float*)d_in[5];
    const float* b1v  = (const float*)d_in[6];
    const float* Wd   = (const float*)d_in[7];
    const float* bd   = (const float*)d_in[8];
    float* out = (float*)d_out;
    (void)b0v;

    init_kernel<<<64, 256>>>();
    transpose_x<<<dim3(TT, 4), 256>>>(x);
    {
        int total = DD * HH * 4 + 3 * HH * HH * 4;
        transpose_w<<<(total + 255) / 256, 256>>>(Wih0, Whh0, Wih1, Whh1);
    }
    xg0_kernel<<<TT * 32, 128>>>(b0v);
    lstm_persist<<<NBLK, 128>>>(b1v);
    dense_softmax<<<1, 256>>>(Wd, bd, out);
}

// round 3
// speedup vs baseline: 1.3085x; 1.3085x over previous
#include <cuda_runtime.h>

#define BB 256
#define TT 1024
#define DD 128
#define HH 256
#define CC 10
#define NBLK 128
#define NTHR 256

typedef unsigned long long u64;

// ---------------- device scratch ----------------------------------------------
__device__ float g_xT [(size_t)TT * DD * BB];        // [t][d][b]
__device__ float g_xg0[(size_t)TT * HH * 4 * BB];    // [t][u][g][b]
__device__ float g_h0[2][HH * BB];                   // ping-pong [u][b]
__device__ float g_h1[2][HH * BB];
__device__ float g_Wt_ih0[DD * HH * 4];              // [k][u][g]
__device__ float g_Wt_hh0[HH * HH * 4];
__device__ float g_Wt_ih1[HH * HH * 4];
__device__ float g_Wt_hh1[HH * HH * 4];
__device__ unsigned g_arrive;
__device__ unsigned g_release;

// ---------------- packed fp32x2 helpers ----------------------------------------
__device__ __forceinline__ u64 dup2(float w) {
    u64 r; asm("mov.b64 %0,{%1,%1};" : "=l"(r) : "f"(w)); return r;
}
__device__ __forceinline__ void pfma(u64& d, u64 a, u64 b) {
    asm("fma.rn.f32x2 %0,%1,%2,%0;" : "+l"(d) : "l"(a), "l"(b));
}
__device__ __forceinline__ float2 unpk(u64 v) {
    float2 f; asm("mov.b64 {%0,%1},%2;" : "=f"(f.x), "=f"(f.y) : "l"(v)); return f;
}
__device__ __forceinline__ float sigm(float x) { return 1.f / (1.f + __expf(-x)); }
__device__ __forceinline__ float tanh_(float x) { return 1.f - 2.f / (__expf(2.f * x) + 1.f); }

// ---------------- init (every replay) ------------------------------------------
__global__ void init_kernel() {
    int n = HH * BB;
    for (int i = blockIdx.x * blockDim.x + threadIdx.x; i < n; i += gridDim.x * blockDim.x) {
        g_h0[0][i] = 0.f;
        g_h1[0][i] = 0.f;
    }
    if (blockIdx.x == 0 && threadIdx.x == 0) { g_arrive = 0u; g_release = 0u; }
}

// ---------------- x transpose: xT[t][d][b] = x[b][t][d] -------------------------
__global__ __launch_bounds__(256) void transpose_x(const float* __restrict__ x) {
    __shared__ float tile[64][33];
    const int t = blockIdx.x, b0 = blockIdx.y * 64;
    for (int dc = 0; dc < DD; dc += 32) {
        for (int i = threadIdx.x; i < 64 * 32; i += 256) {
            int bi = i >> 5, di = i & 31;
            tile[bi][di] = x[((size_t)(b0 + bi) * TT + t) * DD + dc + di];
        }
        __syncthreads();
        for (int i = threadIdx.x; i < 64 * 32; i += 256) {
            int di = i >> 6, bi = i & 63;
            g_xT[((size_t)t * DD + dc + di) * BB + b0 + bi] = tile[bi][di];
        }
        __syncthreads();
    }
}

// ---------------- weight transpose: Wt[k][u][g] = W[g*HH+u][k] ------------------
__global__ void transpose_w(const float* __restrict__ Wih0, const float* __restrict__ Whh0,
                            const float* __restrict__ Wih1, const float* __restrict__ Whh1) {
    const int NI = DD * HH * 4, NH = HH * HH * 4;
    int idx = blockIdx.x * blockDim.x + threadIdx.x;
    if (idx < NI) {
        int g = idx & 3, u = (idx >> 2) & 255, k = idx >> 10;
        g_Wt_ih0[idx] = Wih0[(g * HH + u) * DD + k];
    } else if (idx < NI + 3 * NH) {
        int j = idx - NI, m = j / NH, r = j % NH;
        int g = r & 3, u = (r >> 2) & 255, k = r >> 10;
        if (m == 0)      g_Wt_hh0[r] = Whh0[(g * HH + u) * HH + k];
        else if (m == 1) g_Wt_ih1[r] = Wih1[(g * HH + u) * HH + k];
        else             g_Wt_hh1[r] = Whh1[(g * HH + u) * HH + k];
    }
}

// ---------------- xg0 = x @ Wih0^T + b0, layout [t][u][g][b] --------------------
__device__ __forceinline__ void gemm_2u(const float* __restrict__ A,
                                        const float* __restrict__ Wt,
                                        int K, int bofs, int u0, u64 acc[2][4][4]) {
#pragma unroll 2
    for (int k = 0; k < K; ++k) {
        ulonglong2 a0 = *(const ulonglong2*)(A + (size_t)k * BB + bofs);
        ulonglong2 a1 = *(const ulonglong2*)(A + (size_t)k * BB + bofs + 4);
        float4 w0 = *(const float4*)(Wt + ((size_t)k * HH + u0) * 4);
        float4 w1 = *(const float4*)(Wt + ((size_t)k * HH + u0 + 1) * 4);
        u64 a[4] = {a0.x, a0.y, a1.x, a1.y};
        float wv0[4] = {w0.x, w0.y, w0.z, w0.w};
        float wv1[4] = {w1.x, w1.y, w1.z, w1.w};
#pragma unroll
        for (int g = 0; g < 4; ++g) {
            u64 wp = dup2(wv0[g]);
#pragma unroll
            for (int p = 0; p < 4; ++p) pfma(acc[0][g][p], a[p], wp);
        }
#pragma unroll
        for (int g = 0; g < 4; ++g) {
            u64 wp = dup2(wv1[g]);
#pragma unroll
            for (int p = 0; p < 4; ++p) pfma(acc[1][g][p], a[p], wp);
        }
    }
}

__global__ __launch_bounds__(128) void xg0_kernel(const float* __restrict__ b0v) {
    const int bid = blockIdx.x;
    const int t = bid >> 5, sub = bid & 31;
    const int ub = sub >> 2, bb = sub & 3;
    const int m_t = threadIdx.x & 7, n_t = threadIdx.x >> 3;
    const int u0 = ub * 32 + n_t * 2;
    const int bofs = bb * 64 + m_t * 8;

    u64 acc[2][4][4];
#pragma unroll
    for (int uu = 0; uu < 2; ++uu)
#pragma unroll
        for (int g = 0; g < 4; ++g) {
            u64 bp = dup2(b0v[g * HH + u0 + uu]);
#pragma unroll
            for (int p = 0; p < 4; ++p) acc[uu][g][p] = bp;
        }
    gemm_2u(g_xT + (size_t)t * DD * BB, g_Wt_ih0, DD, bofs, u0, acc);

    float* X = g_xg0 + (size_t)t * HH * 4 * BB;
#pragma unroll
    for (int uu = 0; uu < 2; ++uu)
#pragma unroll
        for (int g = 0; g < 4; ++g) {
            float* dst = X + (((size_t)(u0 + uu) * 4) + g) * BB + bofs;
            ulonglong2 v0; v0.x = acc[uu][g][0]; v0.y = acc[uu][g][1];
            ulonglong2 v1; v1.x = acc[uu][g][2]; v1.y = acc[uu][g][3];
            *(ulonglong2*)dst = v0;
            *(ulonglong2*)(dst + 4) = v1;
        }
}

// ---------------- software grid barrier ----------------------------------------
__device__ __forceinline__ void grid_barrier(unsigned gen) {
    __syncthreads();
    if (threadIdx.x == 0) {
        __threadfence();
        unsigned prev = atomicAdd(&g_arrive, 1u);
        if (prev == NBLK - 1u) {
            g_arrive = 0u;
            __threadfence();
            *(volatile unsigned*)&g_release = gen;
        } else {
            while (*(volatile unsigned*)&g_release < gen) __nanosleep(32);
            __threadfence();
        }
    }
    __syncthreads();
}

// ---------------- persistent-kernel inner GEMM ----------------------------------
// acc[g] += A[k][bofs pair] * Wsmem[k][u_t][g]  over k = 0..255
__device__ __forceinline__ void gemm256(const float* __restrict__ A,
                                        const u64* __restrict__ W,
                                        int aofs, int u_t, u64 acc[4]) {
#pragma unroll 8
    for (int k = 0; k < HH; ++k) {
        u64 a = *(const u64*)(A + (size_t)k * BB + aofs);
        ulonglong2 w01 = *(const ulonglong2*)(W + (k * 8 + u_t) * 4);
        ulonglong2 w23 = *(const ulonglong2*)(W + (k * 8 + u_t) * 4 + 2);
        pfma(acc[0], a, w01.x);
        pfma(acc[1], a, w01.y);
        pfma(acc[2], a, w23.x);
        pfma(acc[3], a, w23.y);
    }
}

// ---------------- persistent LSTM: phase A = L0(t), phase B = L1(t) --------------
__global__ __launch_bounds__(NTHR, 1) void lstm_persist(const float* __restrict__ b1v) {
    extern __shared__ u64 sw[];          // [3][256][8][4]: hh0 | ih1 | hh1 (dup'd)
    const int tid = threadIdx.x;
    const int pair_t = tid & 31;         // 32 batch-pairs (64 batch)
    const int u_t = tid >> 5;            // 8 units
    const int blk = blockIdx.x;          // 128 = 32 u-tiles x 4 b-tiles
    const int ub = blk >> 2;             // unit tile (8 units each)
    const int bofs = (blk & 3) * 64;
    const int aofs = bofs + pair_t * 2;
    const int u = ub * 8 + u_t;

    // one-time: load + duplicate weight slices into smem (persist across steps)
    {
        const float* srcs[3] = {g_Wt_hh0, g_Wt_ih1, g_Wt_hh1};
#pragma unroll
        for (int m = 0; m < 3; ++m) {
            const float* src = srcs[m] + ub * 32;   // [k][u][g]: 32 floats per k for this tile
            u64* dst = sw + m * 8192;
            for (int idx = tid; idx < 8192; idx += NTHR) {
                int k = idx >> 5, r = idx & 31;
                dst[idx] = dup2(src[k * 1024 + r]);
            }
        }
    }
    // L1 gate biases (dup'd, in regs)
    u64 b1d[4];
#pragma unroll
    for (int g = 0; g < 4; ++g) b1d[g] = dup2(b1v[g * HH + u]);

    float c0x = 0.f, c0y = 0.f, c1x = 0.f, c1y = 0.f;
    __syncthreads();

    const u64* sw_hh0 = sw;
    const u64* sw_ih1 = sw + 8192;
    const u64* sw_hh1 = sw + 16384;

    for (int t = 0; t < TT; ++t) {
        const float* h0prev = g_h0[t & 1];
        float*       h0cur  = g_h0[(t + 1) & 1];
        const float* h1prev = g_h1[t & 1];
        float*       h1cur  = g_h1[(t + 1) & 1];

        // ---- phase A: layer 0, step t ----
        {
            u64 acc[4];
            const float* xg = g_xg0 + (((size_t)t * HH + u) * 4) * BB;
#pragma unroll
            for (int g = 0; g < 4; ++g) acc[g] = *(const u64*)(xg + g * BB + aofs);
            gemm256(h0prev, sw_hh0, aofs, u_t, acc);
            float2 iv = unpk(acc[0]), fv = unpk(acc[1]), gv = unpk(acc[2]), ov = unpk(acc[3]);
            c0x = sigm(fv.x) * c0x + sigm(iv.x) * tanh_(gv.x);
            c0y = sigm(fv.y) * c0y + sigm(iv.y) * tanh_(gv.y);
            float2 h = make_float2(sigm(ov.x) * tanh_(c0x), sigm(ov.y) * tanh_(c0y));
            *(float2*)(h0cur + (size_t)u * BB + aofs) = h;
        }
        grid_barrier(2u * t + 1u);

        // ---- phase B: layer 1, step t ----
        {
            u64 acc[4];
#pragma unroll
            for (int g = 0; g < 4; ++g) acc[g] = b1d[g];
            gemm256(h0cur,  sw_ih1, aofs, u_t, acc);
            gemm256(h1prev, sw_hh1, aofs, u_t, acc);
            float2 iv = unpk(acc[0]), fv = unpk(acc[1]), gv = unpk(acc[2]), ov = unpk(acc[3]);
            c1x = sigm(fv.x) * c1x + sigm(iv.x) * tanh_(gv.x);
            c1y = sigm(fv.y) * c1y + sigm(iv.y) * tanh_(gv.y);
            float2 h = make_float2(sigm(ov.x) * tanh_(c1x), sigm(ov.y) * tanh_(c1y));
            *(float2*)(h1cur + (size_t)u * BB + aofs) = h;
        }
        grid_barrier(2u * t + 2u);
    }
}

// ---------------- dense + softmax (final h1 = g_h1[0]) ---------------------------
__global__ __launch_bounds__(256) void dense_softmax(const float* __restrict__ Wd,
                                                     const float* __restrict__ bd,
                                                     float* __restrict__ out) {
    const int b = threadIdx.x;
    const float* h = g_h1[0];
    float acc[CC];
#pragma unroll
    for (int c = 0; c < CC; ++c) acc[c] = bd[c];
    for (int u = 0; u < HH; ++u) {
        float hv = h[(size_t)u * BB + b];
#pragma unroll
        for (int c = 0; c < CC; ++c) acc[c] += hv * Wd[c * HH + u];
    }
    float mx = acc[0];
#pragma unroll
    for (int c = 1; c < CC; ++c) mx = fmaxf(mx, acc[c]);
    float sum = 0.f;
#pragma unroll
    for (int c = 0; c < CC; ++c) { acc[c] = expf(acc[c] - mx); sum += acc[c]; }
    float inv = 1.f / sum;
#pragma unroll
    for (int c = 0; c < CC; ++c) out[b * CC + c] = acc[c] * inv;
}

// ---------------- launch ---------------------------------------------------------
extern "C" void kernel_launch(void* const* d_in, const int* in_sizes, int n_in,
                              void* d_out, int out_size) {
    const float* x    = (const float*)d_in[0];
    const float* Wih0 = (const float*)d_in[1];
    const float* Whh0 = (const float*)d_in[2];
    const float* b0v  = (const float*)d_in[3];
    const float* Wih1 = (const float*)d_in[4];
    const float* Whh1 = (const float*)d_in[5];
    const float* b1v  = (const float*)d_in[6];
    const float* Wd   = (const float*)d_in[7];
    const float* bd   = (const float*)d_in[8];
    float* out = (float*)d_out;

    const int SMEM = 3 * 8192 * (int)sizeof(u64);   // 196608 B
    cudaFuncSetAttribute(lstm_persist, cudaFuncAttributeMaxDynamicSharedMemorySize, SMEM);

    init_kernel<<<64, 256>>>();
    transpose_x<<<dim3(TT, 4), 256>>>(x);
    {
        int total = DD * HH * 4 + 3 * HH * HH * 4;
        transpose_w<<<(total + 255) / 256, 256>>>(Wih0, Whh0, Wih1, Whh1);
    }
    xg0_kernel<<<TT * 32, 128>>>(b0v);
    lstm_persist<<<NBLK, NTHR, SMEM>>>(b1v);
    dense_softmax<<<1, 256>>>(Wd, bd, out);
}

// round 4
// speedup vs baseline: 1.7495x; 1.3370x over previous
#include <cuda_runtime.h>

#define BB 256
#define TT 1024
#define DD 128
#define HH 256
#define CC 10
#define NBLK 128
#define NTHR 256

typedef unsigned long long u64;

// ---------------- device scratch ------------------------------------------------
__device__ float g_xT [(size_t)TT * DD * BB];        // [t][d][b]
__device__ float g_xg0[(size_t)TT * HH * 4 * BB];    // [t][u][g][b]
__device__ float g_h0[2][HH * BB];                   // h0(t) in slot t&1
__device__ float g_h1[2][HH * BB];                   // h1(s) in slot s&1
__device__ float g_Wt_ih0[DD * HH * 4];              // [k][u][g]
__device__ float g_Wt_hh0[HH * HH * 4];
__device__ float g_Wt_ih1[HH * HH * 4];
__device__ float g_Wt_hh1[HH * HH * 4];
__device__ unsigned g_arrive;
__device__ unsigned g_release;

// ---------------- packed fp32x2 helpers ------------------------------------------
__device__ __forceinline__ u64 dup2(float w) {
    u64 r; asm("mov.b64 %0,{%1,%1};" : "=l"(r) : "f"(w)); return r;
}
__device__ __forceinline__ void pfma(u64& d, u64 a, u64 b) {
    asm("fma.rn.f32x2 %0,%1,%2,%0;" : "+l"(d) : "l"(a), "l"(b));
}
__device__ __forceinline__ float2 unpk(u64 v) {
    float2 f; asm("mov.b64 {%0,%1},%2;" : "=f"(f.x), "=f"(f.y) : "l"(v)); return f;
}
__device__ __forceinline__ float sigm(float x) { return 1.f / (1.f + __expf(-x)); }
__device__ __forceinline__ float tanh_(float x) { return 1.f - 2.f / (__expf(2.f * x) + 1.f); }

// ---------------- init (every replay) ---------------------------------------------
__global__ void init_kernel() {
    int n = HH * BB;
    for (int i = blockIdx.x * blockDim.x + threadIdx.x; i < n; i += gridDim.x * blockDim.x) {
        g_h0[1][i] = 0.f;   // h0(-1) = 0
        g_h1[1][i] = 0.f;   // h1(-1) = 0
    }
    if (blockIdx.x == 0 && threadIdx.x == 0) { g_arrive = 0u; g_release = 0u; }
}

// ---------------- prep: x transpose + weight transpose (one kernel) ---------------
__global__ __launch_bounds__(256) void prep_kernel(const float* __restrict__ x,
                                                   const float* __restrict__ Wih0,
                                                   const float* __restrict__ Whh0,
                                                   const float* __restrict__ Wih1,
                                                   const float* __restrict__ Whh1) {
    const int bid = blockIdx.x;
    if (bid < 4096) {
        __shared__ float tile[64][33];
        const int t = bid >> 2, b0 = (bid & 3) * 64;
        for (int dc = 0; dc < DD; dc += 32) {
            for (int i = threadIdx.x; i < 64 * 32; i += 256) {
                int bi = i >> 5, di = i & 31;
                tile[bi][di] = x[((size_t)(b0 + bi) * TT + t) * DD + dc + di];
            }
            __syncthreads();
            for (int i = threadIdx.x; i < 64 * 32; i += 256) {
                int di = i >> 6, bi = i & 63;
                g_xT[((size_t)t * DD + dc + di) * BB + b0 + bi] = tile[bi][di];
            }
            __syncthreads();
        }
    } else {
        const int NI = DD * HH * 4, NH = HH * HH * 4;
        int idx = (bid - 4096) * 256 + threadIdx.x;
        if (idx < NI) {
            int g = idx & 3, u = (idx >> 2) & 255, k = idx >> 10;
            g_Wt_ih0[idx] = Wih0[(g * HH + u) * DD + k];
        } else if (idx < NI + 3 * NH) {
            int j = idx - NI, m = j / NH, r = j % NH;
            int g = r & 3, u = (r >> 2) & 255, k = r >> 10;
            if (m == 0)      g_Wt_hh0[r] = Whh0[(g * HH + u) * HH + k];
            else if (m == 1) g_Wt_ih1[r] = Wih1[(g * HH + u) * HH + k];
            else             g_Wt_hh1[r] = Whh1[(g * HH + u) * HH + k];
        }
    }
}

// ---------------- xg0 = x @ Wih0^T + b0, layout [t][u][g][b] -----------------------
__device__ __forceinline__ void gemm_2u(const float* __restrict__ A,
                                        const float* __restrict__ Wt,
                                        int K, int bofs, int u0, u64 acc[2][4][4]) {
#pragma unroll 2
    for (int k = 0; k < K; ++k) {
        ulonglong2 a0 = *(const ulonglong2*)(A + (size_t)k * BB + bofs);
        ulonglong2 a1 = *(const ulonglong2*)(A + (size_t)k * BB + bofs + 4);
        float4 w0 = *(const float4*)(Wt + ((size_t)k * HH + u0) * 4);
        float4 w1 = *(const float4*)(Wt + ((size_t)k * HH + u0 + 1) * 4);
        u64 a[4] = {a0.x, a0.y, a1.x, a1.y};
        float wv0[4] = {w0.x, w0.y, w0.z, w0.w};
        float wv1[4] = {w1.x, w1.y, w1.z, w1.w};
#pragma unroll
        for (int g = 0; g < 4; ++g) {
            u64 wp = dup2(wv0[g]);
#pragma unroll
            for (int p = 0; p < 4; ++p) pfma(acc[0][g][p], a[p], wp);
        }
#pragma unroll
        for (int g = 0; g < 4; ++g) {
            u64 wp = dup2(wv1[g]);
#pragma unroll
            for (int p = 0; p < 4; ++p) pfma(acc[1][g][p], a[p], wp);
        }
    }
}

__global__ __launch_bounds__(128) void xg0_kernel(const float* __restrict__ b0v) {
    const int bid = blockIdx.x;
    const int t = bid >> 5, sub = bid & 31;
    const int ub = sub >> 2, bb = sub & 3;
    const int m_t = threadIdx.x & 7, n_t = threadIdx.x >> 3;
    const int u0 = ub * 32 + n_t * 2;
    const int bofs = bb * 64 + m_t * 8;

    u64 acc[2][4][4];
#pragma unroll
    for (int uu = 0; uu < 2; ++uu)
#pragma unroll
        for (int g = 0; g < 4; ++g) {
            u64 bp = dup2(b0v[g * HH + u0 + uu]);
#pragma unroll
            for (int p = 0; p < 4; ++p) acc[uu][g][p] = bp;
        }
    gemm_2u(g_xT + (size_t)t * DD * BB, g_Wt_ih0, DD, bofs, u0, acc);

    float* X = g_xg0 + (size_t)t * HH * 4 * BB;
#pragma unroll
    for (int uu = 0; uu < 2; ++uu)
#pragma unroll
        for (int g = 0; g < 4; ++g) {
            float* dst = X + (((size_t)(u0 + uu) * 4) + g) * BB + bofs;
            ulonglong2 v0; v0.x = acc[uu][g][0]; v0.y = acc[uu][g][1];
            ulonglong2 v1; v1.x = acc[uu][g][2]; v1.y = acc[uu][g][3];
            *(ulonglong2*)dst = v0;
            *(ulonglong2*)(dst + 4) = v1;
        }
}

// ---------------- software grid barrier --------------------------------------------
__device__ __forceinline__ void grid_barrier(unsigned gen) {
    __syncthreads();
    if (threadIdx.x == 0) {
        __threadfence();
        unsigned prev = atomicAdd(&g_arrive, 1u);
        if (prev == NBLK - 1u) {
            g_arrive = 0u;
            __threadfence();
            *(volatile unsigned*)&g_release = gen;
        } else {
            while (*(volatile unsigned*)&g_release < gen) __nanosleep(20);
            __threadfence();
        }
    }
    __syncthreads();
}

// ---------------- persistent LSTM ---------------------------------------------------
// smem: sw (dup'd weights, 3 x 256k x 8u x 4g u64 = 192KB) + sa (2 x 32k x 64b f32 = 16KB)
#define SW_ELEMS (3 * 8192)
#define SA_ELEMS (2 * 32 * 64)
#define SMEM_BYTES (SW_ELEMS * 8 + SA_ELEMS * 4)

struct StageRegs { float4 r0, r1; };

// issue global loads for chunk c of A (32 k x 64 b), where A is [k][256] + bbase
__device__ __forceinline__ StageRegs stage_ld(const float* __restrict__ A, int c,
                                              int bbase, int tid) {
    StageRegs s;
    const float* base = A + (size_t)(c * 32) * BB + bbase;
    int i0 = tid * 2, i1 = tid * 2 + 1;
    s.r0 = __ldcg((const float4*)(base + (i0 >> 4) * BB + (i0 & 15) * 4));
    s.r1 = __ldcg((const float4*)(base + (i1 >> 4) * BB + (i1 & 15) * 4));
    return s;
}
__device__ __forceinline__ void stage_st(float* sa, StageRegs s, int tid) {
    int i0 = tid * 2, i1 = tid * 2 + 1;
    *(float4*)(sa + (i0 >> 4) * 64 + (i0 & 15) * 4) = s.r0;
    *(float4*)(sa + (i1 >> 4) * 64 + (i1 & 15) * 4) = s.r1;
}

// compute one 32-k chunk: acc[g] += sa[kk][pair] * sw[kglob][u_t][g]
__device__ __forceinline__ void chunk_mma(const float* __restrict__ sa,
                                          const u64* __restrict__ swk,  // sw + kglob0*32
                                          int pair_t, int u_t, u64 acc[4]) {
#pragma unroll 8
    for (int kk = 0; kk < 32; ++kk) {
        u64 a = *(const u64*)(sa + kk * 64 + pair_t * 2);
        ulonglong2 w01 = *(const ulonglong2*)(swk + kk * 32 + u_t * 4);
        ulonglong2 w23 = *(const ulonglong2*)(swk + kk * 32 + u_t * 4 + 2);
        pfma(acc[0], a, w01.x);
        pfma(acc[1], a, w01.y);
        pfma(acc[2], a, w23.x);
        pfma(acc[3], a, w23.y);
    }
}

// run an N-chunk GEMM pass with double-buffered smem staging.
// srcA(c) gives the global A pointer for chunk c; swbase points at matrix 0 of the pass.
template <int NC>
__device__ __forceinline__ void gemm_pass(const float* __restrict__ A0,
                                          const float* __restrict__ A1,  // second source (c>=8) or null
                                          const u64* __restrict__ swbase,
                                          float* __restrict__ sa,
                                          int bbase, int tid, int pair_t, int u_t,
                                          u64 acc[4]) {
    StageRegs s = stage_ld(A0, 0, bbase, tid);
    stage_st(sa, s, tid);
    __syncthreads();
#pragma unroll
    for (int c = 0; c < NC; ++c) {
        if (c + 1 < NC) {
            const float* src = (c + 1 < 8 || A1 == nullptr) ? A0 : A1;
            int cc = (c + 1 < 8 || A1 == nullptr) ? (c + 1) : (c + 1 - 8);
            s = stage_ld(src, cc, bbase, tid);
        }
        chunk_mma(sa + (c & 1) * (32 * 64), swbase + (size_t)c * 32 * 32, pair_t, u_t, acc);
        if (c + 1 < NC) {
            stage_st(sa + ((c + 1) & 1) * (32 * 64), s, tid);
        }
        __syncthreads();
    }
}

__global__ __launch_bounds__(NTHR, 1) void lstm_persist(const float* __restrict__ b1v) {
    extern __shared__ u64 smem_raw[];
    u64*   sw = smem_raw;                       // 3*8192 u64
    float* sa = (float*)(smem_raw + SW_ELEMS);  // 2*32*64 floats

    const int tid = threadIdx.x;
    const int pair_t = tid & 31;
    const int u_t = tid >> 5;
    const int blk = blockIdx.x;
    const int ub = blk >> 2;
    const int bbase = (blk & 3) * 64;
    const int aofs = bbase + pair_t * 2;
    const int u = ub * 8 + u_t;

    // one-time weight load (dup'd) into smem
    {
        const float* srcs[3] = {g_Wt_hh0, g_Wt_ih1, g_Wt_hh1};
#pragma unroll
        for (int m = 0; m < 3; ++m) {
            const float* src = srcs[m] + ub * 32;
            u64* dst = sw + m * 8192;
            for (int idx = tid; idx < 8192; idx += NTHR) {
                int k = idx >> 5, r = idx & 31;
                dst[idx] = dup2(src[k * 1024 + r]);
            }
        }
    }
    u64 b1d[4];
#pragma unroll
    for (int g = 0; g < 4; ++g) b1d[g] = dup2(b1v[g * HH + u]);

    float c0x = 0.f, c0y = 0.f, c1x = 0.f, c1y = 0.f;
    __syncthreads();

    for (int t = 0; t <= TT; ++t) {
        // ---- L0 step t (phases 0..1023) ----
        if (t < TT) {
            u64 acc[4];
            const float* xg = g_xg0 + (((size_t)t * HH + u) * 4) * BB;
#pragma unroll
            for (int g = 0; g < 4; ++g)
                acc[g] = __ldcg((const u64*)(xg + g * BB + aofs));
            gemm_pass<8>(g_h0[(t + 1) & 1], nullptr, sw, sa, bbase, tid, pair_t, u_t, acc);
            float2 iv = unpk(acc[0]), fv = unpk(acc[1]), gv = unpk(acc[2]), ov = unpk(acc[3]);
            c0x = sigm(fv.x) * c0x + sigm(iv.x) * tanh_(gv.x);
            c0y = sigm(fv.y) * c0y + sigm(iv.y) * tanh_(gv.y);
            __stcg((float2*)(g_h0[t & 1] + (size_t)u * BB + aofs),
                   make_float2(sigm(ov.x) * tanh_(c0x), sigm(ov.y) * tanh_(c0y)));
        }
        // ---- L1 step s = t-1 (phases 1..1024); fused 512-k pass ----
        if (t >= 1) {
            const int s = t - 1;
            u64 acc[4];
#pragma unroll
            for (int g = 0; g < 4; ++g) acc[g] = b1d[g];
            __syncthreads();   // sa reuse between passes
            gemm_pass<16>(g_h0[s & 1], g_h1[(t /* == s+1 -> (s-1)&1 */) & 1],
                          sw + 8192, sa, bbase, tid, pair_t, u_t, acc);
            float2 iv = unpk(acc[0]), fv = unpk(acc[1]), gv = unpk(acc[2]), ov = unpk(acc[3]);
            c1x = sigm(fv.x) * c1x + sigm(iv.x) * tanh_(gv.x);
            c1y = sigm(fv.y) * c1y + sigm(iv.y) * tanh_(gv.y);
            __stcg((float2*)(g_h1[s & 1] + (size_t)u * BB + aofs),
                   make_float2(sigm(ov.x) * tanh_(c1x), sigm(ov.y) * tanh_(c1y)));
        }
        if (t < TT) grid_barrier((unsigned)(t + 1));
    }
}

// ---------------- dense + softmax (final h1(1023) = g_h1[1]) ------------------------
__global__ __launch_bounds__(256) void dense_softmax(const float* __restrict__ Wd,
                                                     const float* __restrict__ bd,
                                                     float* __restrict__ out) {
    const int b = threadIdx.x;
    const float* h = g_h1[1];
    float acc[CC];
#pragma unroll
    for (int c = 0; c < CC; ++c) acc[c] = bd[c];
    for (int u = 0; u < HH; ++u) {
        float hv = h[(size_t)u * BB + b];
#pragma unroll
        for (int c = 0; c < CC; ++c) acc[c] += hv * Wd[c * HH + u];
    }
    float mx = acc[0];
#pragma unroll
    for (int c = 1; c < CC; ++c) mx = fmaxf(mx, acc[c]);
    float sum = 0.f;
#pragma unroll
    for (int c = 0; c < CC; ++c) { acc[c] = expf(acc[c] - mx); sum += acc[c]; }
    float inv = 1.f / sum;
#pragma unroll
    for (int c = 0; c < CC; ++c) out[b * CC + c] = acc[c] * inv;
}

// ---------------- launch --------------------------------------------------------------
extern "C" void kernel_launch(void* const* d_in, const int* in_sizes, int n_in,
                              void* d_out, int out_size) {
    const float* x    = (const float*)d_in[0];
    const float* Wih0 = (const float*)d_in[1];
    const float* Whh0 = (const float*)d_in[2];
    const float* b0v  = (const float*)d_in[3];
    const float* Wih1 = (const float*)d_in[4];
    const float* Whh1 = (const float*)d_in[5];
    const float* b1v  = (const float*)d_in[6];
    const float* Wd   = (const float*)d_in[7];
    const float* bd   = (const float*)d_in[8];
    float* out = (float*)d_out;

    cudaFuncSetAttribute(lstm_persist, cudaFuncAttributeMaxDynamicSharedMemorySize, SMEM_BYTES);

    const int NW = DD * HH * 4 + 3 * HH * HH * 4;
    const int tw_blocks = (NW + 255) / 256;

    init_kernel<<<64, 256>>>();                               // launch 0
    prep_kernel<<<4096 + tw_blocks, 256>>>(x, Wih0, Whh0, Wih1, Whh1);  // launch 1
    xg0_kernel<<<TT * 32, 128>>>(b0v);                        // launch 2
    lstm_persist<<<NBLK, NTHR, SMEM_BYTES>>>(b1v);            // launch 3 (+2 hidden -> ncu -s 5)
    dense_softmax<<<1, 256>>>(Wd, bd, out);                   // launch 4
}

// round 7
// speedup vs baseline: 1.9259x; 1.1008x over previous
#include <cuda_runtime.h>

#define BB 256
#define TT 1024
#define DD 128
#define HH 256
#define CC 10
#define NBLK 128
#define NTHR 512

typedef unsigned long long u64;

// ---------------- device scratch ------------------------------------------------
__device__ float g_xT [(size_t)TT * DD * BB];        // [t][d][b]
__device__ float g_xg0[(size_t)TT * HH * 4 * BB];    // [t][u][g][b]
__device__ float g_h0[2][HH * BB];                   // h0(t) in slot t&1
__device__ float g_h1[2][HH * BB];                   // h1(s) in slot s&1
__device__ float g_Wt_ih0[DD * HH * 4];              // [k][u][g]
__device__ float g_Wt_hh0[HH * HH * 4];
__device__ float g_Wt_ih1[HH * HH * 4];
__device__ float g_Wt_hh1[HH * HH * 4];
__device__ unsigned g_arrive;
__device__ unsigned g_release;

// ---------------- packed fp32x2 helpers ------------------------------------------
__device__ __forceinline__ u64 dup2(float w) {
    u64 r; asm("mov.b64 %0,{%1,%1};" : "=l"(r) : "f"(w)); return r;
}
__device__ __forceinline__ void pfma(u64& d, u64 a, u64 b) {
    asm("fma.rn.f32x2 %0,%1,%2,%0;" : "+l"(d) : "l"(a), "l"(b));
}
__device__ __forceinline__ float2 unpk(u64 v) {
    float2 f; asm("mov.b64 {%0,%1},%2;" : "=f"(f.x), "=f"(f.y) : "l"(v)); return f;
}
__device__ __forceinline__ float sigm(float x) { return 1.f / (1.f + __expf(-x)); }
__device__ __forceinline__ float tanh_(float x) { return 1.f - 2.f / (__expf(2.f * x) + 1.f); }
__device__ __forceinline__ void barhalf(int id) {
    asm volatile("bar.sync %0, 256;" :: "r"(id) : "memory");
}

// ---------------- init (every replay) ---------------------------------------------
__global__ void init_kernel() {
    int n = HH * BB;
    for (int i = blockIdx.x * blockDim.x + threadIdx.x; i < n; i += gridDim.x * blockDim.x) {
        g_h0[1][i] = 0.f;   // h0(-1) = 0
        g_h1[1][i] = 0.f;   // h1(-1) = 0
    }
    if (blockIdx.x == 0 && threadIdx.x == 0) { g_arrive = 0u; g_release = 0u; }
}

// ---------------- prep: x transpose + weight transpose ----------------------------
__global__ __launch_bounds__(256) void prep_kernel(const float* __restrict__ x,
                                                   const float* __restrict__ Wih0,
                                                   const float* __restrict__ Whh0,
                                                   const float* __restrict__ Wih1,
                                                   const float* __restrict__ Whh1) {
    const int bid = blockIdx.x;
    if (bid < 4096) {
        __shared__ float tile[64][33];
        const int t = bid >> 2, b0 = (bid & 3) * 64;
        for (int dc = 0; dc < DD; dc += 32) {
            for (int i = threadIdx.x; i < 64 * 32; i += 256) {
                int bi = i >> 5, di = i & 31;
                tile[bi][di] = x[((size_t)(b0 + bi) * TT + t) * DD + dc + di];
            }
            __syncthreads();
            for (int i = threadIdx.x; i < 64 * 32; i += 256) {
                int di = i >> 6, bi = i & 63;
                g_xT[((size_t)t * DD + dc + di) * BB + b0 + bi] = tile[bi][di];
            }
            __syncthreads();
        }
    } else {
        const int NI = DD * HH * 4, NH = HH * HH * 4;
        int idx = (bid - 4096) * 256 + threadIdx.x;
        if (idx < NI) {
            int g = idx & 3, u = (idx >> 2) & 255, k = idx >> 10;
            g_Wt_ih0[idx] = Wih0[(g * HH + u) * DD + k];
        } else if (idx < NI + 3 * NH) {
            int j = idx - NI, m = j / NH, r = j % NH;
            int g = r & 3, u = (r >> 2) & 255, k = r >> 10;
            if (m == 0)      g_Wt_hh0[r] = Whh0[(g * HH + u) * HH + k];
            else if (m == 1) g_Wt_ih1[r] = Wih1[(g * HH + u) * HH + k];
            else             g_Wt_hh1[r] = Whh1[(g * HH + u) * HH + k];
        }
    }
}

// ---------------- xg0 = x @ Wih0^T + b0, layout [t][u][g][b] -----------------------
__device__ __forceinline__ void gemm_2u(const float* __restrict__ A,
                                        const float* __restrict__ Wt,
                                        int K, int bofs, int u0, u64 acc[2][4][4]) {
#pragma unroll 2
    for (int k = 0; k < K; ++k) {
        ulonglong2 a0 = *(const ulonglong2*)(A + (size_t)k * BB + bofs);
        ulonglong2 a1 = *(const ulonglong2*)(A + (size_t)k * BB + bofs + 4);
        float4 w0 = *(const float4*)(Wt + ((size_t)k * HH + u0) * 4);
        float4 w1 = *(const float4*)(Wt + ((size_t)k * HH + u0 + 1) * 4);
        u64 a[4] = {a0.x, a0.y, a1.x, a1.y};
        float wv0[4] = {w0.x, w0.y, w0.z, w0.w};
        float wv1[4] = {w1.x, w1.y, w1.z, w1.w};
#pragma unroll
        for (int g = 0; g < 4; ++g) {
            u64 wp = dup2(wv0[g]);
#pragma unroll
            for (int p = 0; p < 4; ++p) pfma(acc[0][g][p], a[p], wp);
        }
#pragma unroll
        for (int g = 0; g < 4; ++g) {
            u64 wp = dup2(wv1[g]);
#pragma unroll
            for (int p = 0; p < 4; ++p) pfma(acc[1][g][p], a[p], wp);
        }
    }
}

__global__ __launch_bounds__(128) void xg0_kernel(const float* __restrict__ b0v) {
    const int bid = blockIdx.x;
    const int t = bid >> 5, sub = bid & 31;
    const int ub = sub >> 2, bb = sub & 3;
    const int m_t = threadIdx.x & 7, n_t = threadIdx.x >> 3;
    const int u0 = ub * 32 + n_t * 2;
    const int bofs = bb * 64 + m_t * 8;

    u64 acc[2][4][4];
#pragma unroll
    for (int uu = 0; uu < 2; ++uu)
#pragma unroll
        for (int g = 0; g < 4; ++g) {
            u64 bp = dup2(b0v[g * HH + u0 + uu]);
#pragma unroll
            for (int p = 0; p < 4; ++p) acc[uu][g][p] = bp;
        }
    gemm_2u(g_xT + (size_t)t * DD * BB, g_Wt_ih0, DD, bofs, u0, acc);

    float* X = g_xg0 + (size_t)t * HH * 4 * BB;
#pragma unroll
    for (int uu = 0; uu < 2; ++uu)
#pragma unroll
        for (int g = 0; g < 4; ++g) {
            float* dst = X + (((size_t)(u0 + uu) * 4) + g) * BB + bofs;
            ulonglong2 v0; v0.x = acc[uu][g][0]; v0.y = acc[uu][g][1];
            ulonglong2 v1; v1.x = acc[uu][g][2]; v1.y = acc[uu][g][3];
            *(ulonglong2*)dst = v0;
            *(ulonglong2*)(dst + 4) = v1;
        }
}

// ---------------- software grid barrier --------------------------------------------
__device__ __forceinline__ void grid_barrier(unsigned gen) {
    __syncthreads();
    if (threadIdx.x == 0) {
        __threadfence();
        unsigned prev = atomicAdd(&g_arrive, 1u);
        if (prev == NBLK - 1u) {
            g_arrive = 0u;
            __threadfence();
            *(volatile unsigned*)&g_release = gen;
        } else {
            while (*(volatile unsigned*)&g_release < gen) __nanosleep(20);
            __threadfence();
        }
    }
    __syncthreads();
}

// ---------------- persistent LSTM ---------------------------------------------------
// smem layout (bytes): sw dup'd weights 196608 | sa 4x(16k x 64b) 16384 | red0 8192 | red1 8192
#define SW_U64   (3 * 8192)
#define SMEM_BYTES (SW_U64 * 8 + 4 * 1024 * 4 + 2 * 1024 * 8)

// one 16-k chunk: acc[g] += sa16[kk][pair] * swk[kk][u_t][g]
__device__ __forceinline__ void chunk16(const float* __restrict__ sa16,
                                        const u64* __restrict__ swk,
                                        int pair_t, int u_t, u64 acc[4]) {
#pragma unroll
    for (int kk = 0; kk < 16; ++kk) {
        u64 a = *(const u64*)(sa16 + kk * 64 + pair_t * 2);
        ulonglong2 w01 = *(const ulonglong2*)(swk + kk * 32 + u_t * 4);
        ulonglong2 w23 = *(const ulonglong2*)(swk + kk * 32 + u_t * 4 + 2);
        pfma(acc[0], a, w01.x);
        pfma(acc[1], a, w01.y);
        pfma(acc[2], a, w23.x);
        pfma(acc[3], a, w23.y);
    }
}

// NC-chunk GEMM pass for one warp-half, double-buffered, half-scoped barrier.
// A = source base (already offset by bbase and k-offset); chunk c covers k = c*16..
template <int NC>
__device__ __forceinline__ void half_pass(const float* __restrict__ A,
                                          const u64* __restrict__ swb,
                                          float* __restrict__ buf0, float* __restrict__ buf1,
                                          int barid, int htid, int pair_t, int u_t,
                                          u64 acc[4]) {
    const int row = htid >> 4, col = (htid & 15) * 4;
    float4 v = __ldcg((const float4*)(A + (size_t)row * BB + col));
    *(float4*)(buf0 + row * 64 + col) = v;
    barhalf(barid);
#pragma unroll
    for (int c = 0; c < NC; ++c) {
        float* cur = (c & 1) ? buf1 : buf0;
        float* nxt = (c & 1) ? buf0 : buf1;
        float4 w;
        if (c + 1 < NC)
            w = __ldcg((const float4*)(A + (size_t)((c + 1) * 16 + row) * BB + col));
        chunk16(cur, swb + (size_t)c * 512, pair_t, u_t, acc);
        if (c + 1 < NC) {
            *(float4*)(nxt + row * 64 + col) = w;
            barhalf(barid);
        }
    }
}

__global__ __launch_bounds__(NTHR, 1) void lstm_persist(const float* __restrict__ b1v) {
    extern __shared__ u64 smem_raw[];
    u64*   sw   = smem_raw;                         // 3*8192 u64
    float* sa   = (float*)(smem_raw + SW_U64);      // 4*1024 floats
    u64*   red0 = (u64*)(sa + 4 * 1024);            // 1024 u64
    u64*   red1 = red0 + 1024;                      // 1024 u64

    const int tid = threadIdx.x;
    const int kh = tid >> 8;             // warp-half: 0 or 1
    const int htid = tid & 255;
    const int pair_t = htid & 31;
    const int u_t = htid >> 5;
    const int blk = blockIdx.x;
    const int ub = blk >> 2;
    const int bbase = (blk & 3) * 64;
    const int aofs = bbase + pair_t * 2;
    const int u = ub * 8 + u_t;
    const int barid = 1 + kh;
    float* buf0 = sa + kh * 2048;
    float* buf1 = buf0 + 1024;

    // one-time weight load (dup'd) into smem
    {
        const float* srcs[3] = {g_Wt_hh0, g_Wt_ih1, g_Wt_hh1};
#pragma unroll
        for (int m = 0; m < 3; ++m) {
            const float* src = srcs[m] + ub * 32;
            u64* dst = sw + m * 8192;
            for (int idx = tid; idx < 8192; idx += NTHR) {
                int k = idx >> 5, r = idx & 31;
                dst[idx] = dup2(src[k * 1024 + r]);
            }
        }
    }
    u64 b1d[4];
#pragma unroll
    for (int g = 0; g < 4; ++g) b1d[g] = dup2(b1v[g * HH + u]);

    float c0x = 0.f, c0y = 0.f, c1x = 0.f, c1y = 0.f;
    __syncthreads();

    for (int t = 0; t <= TT; ++t) {
        // ---- L0 step t: kh0 k[0,128) + xg init; kh1 k[128,256) ----
        if (t < TT) {
            u64 acc[4];
            if (kh == 0) {
                const float* xg = g_xg0 + (((size_t)t * HH + u) * 4) * BB;
#pragma unroll
                for (int g = 0; g < 4; ++g)
                    acc[g] = __ldcg((const u64*)(xg + g * BB + aofs));
            } else {
#pragma unroll
                for (int g = 0; g < 4; ++g) acc[g] = 0ull;
            }
            const float* A = g_h0[(t + 1) & 1] + bbase + (kh ? 128 * BB : 0);
            half_pass<8>(A, sw + kh * 4096, buf0, buf1, barid, htid, pair_t, u_t, acc);
            if (kh == 1) {
#pragma unroll
                for (int g = 0; g < 4; ++g) red0[g * 256 + htid] = acc[g];
            }
            __syncthreads();
            if (kh == 0) {
#pragma unroll
                for (int g = 0; g < 4; ++g) {
                    u64 r = red0[g * 256 + htid];
                    float2 pa = unpk(acc[g]), pb = unpk(r);
                    acc[g] = 0; // repack
                    u64 s; asm("mov.b64 %0,{%1,%2};" : "=l"(s) : "f"(pa.x + pb.x), "f"(pa.y + pb.y));
                    acc[g] = s;
                }
                float2 iv = unpk(acc[0]), fv = unpk(acc[1]), gv = unpk(acc[2]), ov = unpk(acc[3]);
                c0x = sigm(fv.x) * c0x + sigm(iv.x) * tanh_(gv.x);
                c0y = sigm(fv.y) * c0y + sigm(iv.y) * tanh_(gv.y);
                __stcg((float2*)(g_h0[t & 1] + (size_t)u * BB + aofs),
                       make_float2(sigm(ov.x) * tanh_(c0x), sigm(ov.y) * tanh_(c0y)));
            }
        }
        // ---- L1 step s=t-1: kh0 = ih1 (src h0(t-1)); kh1 = hh1 (src h1(t-2)) ----
        if (t >= 1) {
            u64 acc[4];
            if (kh == 0) {
#pragma unroll
                for (int g = 0; g < 4; ++g) acc[g] = b1d[g];
            } else {
#pragma unroll
                for (int g = 0; g < 4; ++g) acc[g] = 0ull;
            }
            const float* A = (kh == 0 ? g_h0[(t + 1) & 1] : g_h1[t & 1]) + bbase;
            const u64* swb = sw + 8192 + kh * 8192;
            half_pass<16>(A, swb, buf0, buf1, barid, htid, pair_t, u_t, acc);
            if (kh == 1) {
#pragma unroll
                for (int g = 0; g < 4; ++g) red1[g * 256 + htid] = acc[g];
            }
            __syncthreads();
            if (kh == 0) {
#pragma unroll
                for (int g = 0; g < 4; ++g) {
                    u64 r = red1[g * 256 + htid];
                    float2 pa = unpk(acc[g]), pb = unpk(r);
                    u64 s; asm("mov.b64 %0,{%1,%2};" : "=l"(s) : "f"(pa.x + pb.x), "f"(pa.y + pb.y));
                    acc[g] = s;
                }
                float2 iv = unpk(acc[0]), fv = unpk(acc[1]), gv = unpk(acc[2]), ov = unpk(acc[3]);
                c1x = sigm(fv.x) * c1x + sigm(iv.x) * tanh_(gv.x);
                c1y = sigm(fv.y) * c1y + sigm(iv.y) * tanh_(gv.y);
                __stcg((float2*)(g_h1[(t + 1) & 1] + (size_t)u * BB + aofs),
                       make_float2(sigm(ov.x) * tanh_(c1x), sigm(ov.y) * tanh_(c1y)));
            }
        }
        if (t < TT) grid_barrier((unsigned)(t + 1));
    }
}

// ---------------- dense + softmax (final h1(1023) = g_h1[1]) ------------------------
__global__ __launch_bounds__(256) void dense_softmax(const float* __restrict__ Wd,
                                                     const float* __restrict__ bd,
                                                     float* __restrict__ out) {
    const int b = threadIdx.x;
    const float* h = g_h1[1];
    float acc[CC];
#pragma unroll
    for (int c = 0; c < CC; ++c) acc[c] = bd[c];
    for (int u = 0; u < HH; ++u) {
        float hv = h[(size_t)u * BB + b];
#pragma unroll
        for (int c = 0; c < CC; ++c) acc[c] += hv * Wd[c * HH + u];
    }
    float mx = acc[0];
#pragma unroll
    for (int c = 1; c < CC; ++c) mx = fmaxf(mx, acc[c]);
    float sum = 0.f;
#pragma unroll
    for (int c = 0; c < CC; ++c) { acc[c] = expf(acc[c] - mx); sum += acc[c]; }
    float inv = 1.f / sum;
#pragma unroll
    for (int c = 0; c < CC; ++c) out[b * CC + c] = acc[c] * inv;
}

// ---------------- launch --------------------------------------------------------------
extern "C" void kernel_launch(void* const* d_in, const int* in_sizes, int n_in,
                              void* d_out, int out_size) {
    const float* x    = (const float*)d_in[0];
    const float* Wih0 = (const float*)d_in[1];
    const float* Whh0 = (const float*)d_in[2];
    const float* b0v  = (const float*)d_in[3];
    const float* Wih1 = (const float*)d_in[4];
    const float* Whh1 = (const float*)d_in[5];
    const float* b1v  = (const float*)d_in[6];
    const float* Wd   = (const float*)d_in[7];
    const float* bd   = (const float*)d_in[8];
    float* out = (float*)d_out;

    cudaFuncSetAttribute(lstm_persist, cudaFuncAttributeMaxDynamicSharedMemorySize, SMEM_BYTES);

    const int NW = DD * HH * 4 + 3 * HH * HH * 4;
    const int tw_blocks = (NW + 255) / 256;

    init_kernel<<<64, 256>>>();                                         // 0
    prep_kernel<<<4096 + tw_blocks, 256>>>(x, Wih0, Whh0, Wih1, Whh1);  // 1
    xg0_kernel<<<TT * 32, 128>>>(b0v);                                  // 2
    lstm_persist<<<NBLK, NTHR, SMEM_BYTES>>>(b1v);                      // 3
    dense_softmax<<<1, 256>>>(Wd, bd, out);                             // 4
}

// round 9
// speedup vs baseline: 1.9559x; 1.0156x over previous
#include <cuda_runtime.h>

#define BB 256
#define TT 1024
#define DD 128
#define HH 256
#define CC 10
#define NBLK 128     // 32 unit-blocks x 4 batch-groups
#define NTHR 256

typedef unsigned long long u64;

// ---------------- device scratch ------------------------------------------------
__device__ float g_xT [(size_t)TT * DD * BB];        // [t][d][b]
__device__ float g_xg0[(size_t)TT * HH * 4 * BB];    // [t][u][g][b]
__device__ float g_h0[2][HH * BB];                   // h0(t) in slot t&1
__device__ float g_h1[2][HH * BB];                   // h1(s) in slot s&1
__device__ float g_Wt_ih0[DD * HH * 4];              // [k][u][g]
__device__ float g_Wt_hh0[HH * HH * 4];
__device__ float g_Wt_ih1[HH * HH * 4];
__device__ float g_Wt_hh1[HH * HH * 4];
__device__ unsigned g_flags[4][32];                  // [batch-group][unit-block]
__device__ unsigned g_rel[4];

// ---------------- packed fp32x2 helpers ------------------------------------------
__device__ __forceinline__ u64 dup2(float w) {
    u64 r; asm("mov.b64 %0,{%1,%1};" : "=l"(r) : "f"(w)); return r;
}
__device__ __forceinline__ void pfma(u64& d, u64 a, u64 b) {
    asm("fma.rn.f32x2 %0,%1,%2,%0;" : "+l"(d) : "l"(a), "l"(b));
}
__device__ __forceinline__ u64 padd(u64 a, u64 b) {
    u64 r; asm("add.rn.f32x2 %0,%1,%2;" : "=l"(r) : "l"(a), "l"(b)); return r;
}
__device__ __forceinline__ float2 unpk(u64 v) {
    float2 f; asm("mov.b64 {%0,%1},%2;" : "=f"(f.x), "=f"(f.y) : "l"(v)); return f;
}
__device__ __forceinline__ float sigm(float x) { return 1.f / (1.f + __expf(-x)); }
__device__ __forceinline__ float tanh_(float x) { return 1.f - 2.f / (__expf(2.f * x) + 1.f); }

__device__ __forceinline__ void cpa16(void* smem_dst, const void* gsrc) {
    unsigned su = (unsigned)__cvta_generic_to_shared(smem_dst);
    asm volatile("cp.async.cg.shared.global [%0], [%1], 16;" :: "r"(su), "l"(gsrc) : "memory");
}
__device__ __forceinline__ void cpa_commit() {
    asm volatile("cp.async.commit_group;" ::: "memory");
}

// ---------------- init (every replay) ---------------------------------------------
__global__ void init_kernel() {
    int n = HH * BB;
    for (int i = blockIdx.x * blockDim.x + threadIdx.x; i < n; i += gridDim.x * blockDim.x) {
        g_h0[1][i] = 0.f;   // h0(-1)
        g_h1[1][i] = 0.f;   // h1(-1)
        g_h1[0][i] = 0.f;   // (read as garbage source at t=0; keep deterministic)
    }
    int idx = blockIdx.x * blockDim.x + threadIdx.x;
    if (idx < 128) g_flags[idx >> 5][idx & 31] = 0u;
    if (idx < 4) g_rel[idx] = 0u;
}

// ---------------- prep: x transpose + weight transpose ----------------------------
__global__ __launch_bounds__(256) void prep_kernel(const float* __restrict__ x,
                                                   const float* __restrict__ Wih0,
                                                   const float* __restrict__ Whh0,
                                                   const float* __restrict__ Wih1,
                                                   const float* __restrict__ Whh1) {
    const int bid = blockIdx.x;
    if (bid < 4096) {
        __shared__ float tile[64][33];
        const int t = bid >> 2, b0 = (bid & 3) * 64;
        for (int dc = 0; dc < DD; dc += 32) {
            for (int i = threadIdx.x; i < 64 * 32; i += 256) {
                int bi = i >> 5, di = i & 31;
                tile[bi][di] = x[((size_t)(b0 + bi) * TT + t) * DD + dc + di];
            }
            __syncthreads();
            for (int i = threadIdx.x; i < 64 * 32; i += 256) {
                int di = i >> 6, bi = i & 63;
                g_xT[((size_t)t * DD + dc + di) * BB + b0 + bi] = tile[bi][di];
            }
            __syncthreads();
        }
    } else {
        const int NI = DD * HH * 4, NH = HH * HH * 4;
        int idx = (bid - 4096) * 256 + threadIdx.x;
        if (idx < NI) {
            int g = idx & 3, u = (idx >> 2) & 255, k = idx >> 10;
            g_Wt_ih0[idx] = Wih0[(g * HH + u) * DD + k];
        } else if (idx < NI + 3 * NH) {
            int j = idx - NI, m = j / NH, r = j % NH;
            int g = r & 3, u = (r >> 2) & 255, k = r >> 10;
            if (m == 0)      g_Wt_hh0[r] = Whh0[(g * HH + u) * HH + k];
            else if (m == 1) g_Wt_ih1[r] = Wih1[(g * HH + u) * HH + k];
            else             g_Wt_hh1[r] = Whh1[(g * HH + u) * HH + k];
        }
    }
}

// ---------------- xg0 = x @ Wih0^T + b0, layout [t][u][g][b] -----------------------
__device__ __forceinline__ void gemm_2u(const float* __restrict__ A,
                                        const float* __restrict__ Wt,
                                        int K, int bofs, int u0, u64 acc[2][4][4]) {
#pragma unroll 2
    for (int k = 0; k < K; ++k) {
        ulonglong2 a0 = *(const ulonglong2*)(A + (size_t)k * BB + bofs);
        ulonglong2 a1 = *(const ulonglong2*)(A + (size_t)k * BB + bofs + 4);
        float4 w0 = *(const float4*)(Wt + ((size_t)k * HH + u0) * 4);
        float4 w1 = *(const float4*)(Wt + ((size_t)k * HH + u0 + 1) * 4);
        u64 a[4] = {a0.x, a0.y, a1.x, a1.y};
        float wv0[4] = {w0.x, w0.y, w0.z, w0.w};
        float wv1[4] = {w1.x, w1.y, w1.z, w1.w};
#pragma unroll
        for (int g = 0; g < 4; ++g) {
            u64 wp = dup2(wv0[g]);
#pragma unroll
            for (int p = 0; p < 4; ++p) pfma(acc[0][g][p], a[p], wp);
        }
#pragma unroll
        for (int g = 0; g < 4; ++g) {
            u64 wp = dup2(wv1[g]);
#pragma unroll
            for (int p = 0; p < 4; ++p) pfma(acc[1][g][p], a[p], wp);
        }
    }
}

__global__ __launch_bounds__(128) void xg0_kernel(const float* __restrict__ b0v) {
    const int bid = blockIdx.x;
    const int t = bid >> 5, sub = bid & 31;
    const int ub = sub >> 2, bb = sub & 3;
    const int m_t = threadIdx.x & 7, n_t = threadIdx.x >> 3;
    const int u0 = ub * 32 + n_t * 2;
    const int bofs = bb * 64 + m_t * 8;

    u64 acc[2][4][4];
#pragma unroll
    for (int uu = 0; uu < 2; ++uu)
#pragma unroll
        for (int g = 0; g < 4; ++g) {
            u64 bp = dup2(b0v[g * HH + u0 + uu]);
#pragma unroll
            for (int p = 0; p < 4; ++p) acc[uu][g][p] = bp;
        }
    gemm_2u(g_xT + (size_t)t * DD * BB, g_Wt_ih0, DD, bofs, u0, acc);

    float* X = g_xg0 + (size_t)t * HH * 4 * BB;
#pragma unroll
    for (int uu = 0; uu < 2; ++uu)
#pragma unroll
        for (int g = 0; g < 4; ++g) {
            float* dst = X + (((size_t)(u0 + uu) * 4) + g) * BB + bofs;
            ulonglong2 v0; v0.x = acc[uu][g][0]; v0.y = acc[uu][g][1];
            ulonglong2 v1; v1.x = acc[uu][g][2]; v1.y = acc[uu][g][3];
            *(ulonglong2*)dst = v0;
            *(ulonglong2*)(dst + 4) = v1;
        }
}

// ---------------- grouped grid barrier (4 independent groups of 32 blocks) ---------
__device__ __forceinline__ void group_barrier(int bb, int ub, unsigned gen) {
    __threadfence();
    __syncthreads();
    if (threadIdx.x == 0) *(volatile unsigned*)&g_flags[bb][ub] = gen;
    if (ub == 0 && threadIdx.x < 32) {
        while (*(volatile unsigned*)&g_flags[bb][threadIdx.x] < gen) __nanosleep(20);
        __syncwarp();
        if (threadIdx.x == 0) {
            __threadfence();
            *(volatile unsigned*)&g_rel[bb] = gen;
        }
    }
    if (threadIdx.x == 0) {
        while (*(volatile unsigned*)&g_rel[bb] < gen) __nanosleep(20);
        __threadfence();
    }
    __syncthreads();
}

// ---------------- persistent LSTM ---------------------------------------------------
// smem: dup'd weights 3 x 8192 u64 (192KB) + a-ring 3 x (32k x 64b) f32 (24KB) = 216KB
#define SW_U64     (3 * 8192)
#define RING_F32   (3 * 2048)
#define SMEM_BYTES (SW_U64 * 8 + RING_F32 * 4)

// stage one 8KB chunk (32 k-rows x 64 floats) via cp.async
__device__ __forceinline__ void stage_chunk(float* buf, const float* src, int tid) {
    int s0 = tid * 2, s1 = s0 + 1;
    cpa16(buf + (s0 >> 4) * 64 + (s0 & 15) * 4, src + (size_t)(s0 >> 4) * BB + (s0 & 15) * 4);
    cpa16(buf + (s1 >> 4) * 64 + (s1 & 15) * 4, src + (size_t)(s1 >> 4) * BB + (s1 & 15) * 4);
    cpa_commit();
}

__global__ __launch_bounds__(NTHR, 1) void lstm_persist(const float* __restrict__ b1v) {
    extern __shared__ u64 smem_raw[];
    u64*   sw_hh0 = smem_raw;
    u64*   sw_ih1 = smem_raw + 8192;
    u64*   sw_hh1 = smem_raw + 16384;
    float* ring   = (float*)(smem_raw + SW_U64);

    const int tid  = threadIdx.x;
    const int warp = tid >> 5, lane = tid & 31;
    const int pl = lane & 15, ul = lane >> 4;
    const int pg = warp & 1,  ug = warp >> 1;
    const int pair = pg * 16 + pl;         // 0..31
    const int uloc = ug * 2 + ul;          // 0..7
    const int ub = blockIdx.x >> 2, bb = blockIdx.x & 3;
    const int u = ub * 8 + uloc;
    const int bbase = bb * 64;
    const int aofs = bbase + pair * 2;

    // one-time dup'd weight load into smem: sw[(k*8+uloc)*4+g] = dup(W[k][ub*8+uloc][g])
    {
        const float* srcs[3] = {g_Wt_hh0, g_Wt_ih1, g_Wt_hh1};
        u64* dsts[3] = {sw_hh0, sw_ih1, sw_hh1};
#pragma unroll
        for (int m = 0; m < 3; ++m) {
            const float* src = srcs[m] + ub * 32;
            u64* dst = dsts[m];
            for (int idx = tid; idx < 8192; idx += NTHR) {
                int k = idx >> 5, r = idx & 31;
                dst[idx] = dup2(src[(size_t)k * 1024 + r]);
            }
        }
    }
    u64 b1d[4];
#pragma unroll
    for (int g = 0; g < 4; ++g) b1d[g] = dup2(b1v[g * HH + u]);

    float c0x = 0.f, c0y = 0.f, c1x = 0.f, c1y = 0.f;
    __syncthreads();

    for (int t = 0; t <= TT; ++t) {
        const float* h0p  = g_h0[(t + 1) & 1] + bbase;   // h0(t-1)
        const float* h1p2 = g_h1[t & 1]       + bbase;   // h1(t-2)

        // prefetch xg(t) off the critical path
        u64 xgr[4];
        if (t < TT) {
            const float* xg = g_xg0 + (((size_t)t * HH + u) * 4) * BB + aofs;
#pragma unroll
            for (int g = 0; g < 4; ++g)
                xgr[g] = __ldcg((const u64*)(xg + (size_t)g * BB));
        }

        // prologue: 2 chunks in flight
        stage_chunk(ring,        h0p, tid);
        stage_chunk(ring + 2048, h0p + 32 * BB, tid);

        u64 acc0[4] = {0, 0, 0, 0}, acc1[4] = {0, 0, 0, 0};

        for (int c = 0; c < 16; ++c) {
            if (c + 2 < 16) {
                const float* nsrc = (c + 2 < 8) ? (h0p + (size_t)(c + 2) * 32 * BB)
                                                : (h1p2 + (size_t)(c - 6) * 32 * BB);
                stage_chunk(ring + ((c + 2) % 3) * 2048, nsrc, tid);
                asm volatile("cp.async.wait_group 2;" ::: "memory");
            } else if (c + 1 < 16) {
                asm volatile("cp.async.wait_group 1;" ::: "memory");
            } else {
                asm volatile("cp.async.wait_group 0;" ::: "memory");
            }
            __syncthreads();
            const float* bf = ring + (c % 3) * 2048;
            if (c < 8) {
                const u64* w0 = sw_hh0 + (size_t)c * 1024;
                const u64* w1 = sw_ih1 + (size_t)c * 1024;
#pragma unroll 8
                for (int kk = 0; kk < 32; ++kk) {
                    u64 a = *(const u64*)(bf + kk * 64 + pair * 2);
                    ulonglong2 wa = *(const ulonglong2*)(w0 + kk * 32 + uloc * 4);
                    ulonglong2 wb = *(const ulonglong2*)(w0 + kk * 32 + uloc * 4 + 2);
                    ulonglong2 wc = *(const ulonglong2*)(w1 + kk * 32 + uloc * 4);
                    ulonglong2 wd = *(const ulonglong2*)(w1 + kk * 32 + uloc * 4 + 2);
                    pfma(acc0[0], a, wa.x); pfma(acc0[1], a, wa.y);
                    pfma(acc0[2], a, wb.x); pfma(acc0[3], a, wb.y);
                    pfma(acc1[0], a, wc.x); pfma(acc1[1], a, wc.y);
                    pfma(acc1[2], a, wd.x); pfma(acc1[3], a, wd.y);
                }
            } else {
                const u64* w2 = sw_hh1 + (size_t)(c - 8) * 1024;
#pragma unroll 8
                for (int kk = 0; kk < 32; ++kk) {
                    u64 a = *(const u64*)(bf + kk * 64 + pair * 2);
                    ulonglong2 wa = *(const ulonglong2*)(w2 + kk * 32 + uloc * 4);
                    ulonglong2 wb = *(const ulonglong2*)(w2 + kk * 32 + uloc * 4 + 2);
                    pfma(acc1[0], a, wa.x); pfma(acc1[1], a, wa.y);
                    pfma(acc1[2], a, wb.x); pfma(acc1[3], a, wb.y);
                }
            }
        }

        // pointwise L0: h0(t)
        if (t < TT) {
            float2 iv = unpk(padd(acc0[0], xgr[0]));
            float2 fv = unpk(padd(acc0[1], xgr[1]));
            float2 gv = unpk(padd(acc0[2], xgr[2]));
            float2 ov = unpk(padd(acc0[3], xgr[3]));
            c0x = sigm(fv.x) * c0x + sigm(iv.x) * tanh_(gv.x);
            c0y = sigm(fv.y) * c0y + sigm(iv.y) * tanh_(gv.y);
            __stcg((float2*)(g_h0[t & 1] + (size_t)u * BB + aofs),
                   make_float2(sigm(ov.x) * tanh_(c0x), sigm(ov.y) * tanh_(c0y)));
        }
        // pointwise L1: h1(t-1)
        if (t >= 1) {
            float2 iv = unpk(padd(acc1[0], b1d[0]));
            float2 fv = unpk(padd(acc1[1], b1d[1]));
            float2 gv = unpk(padd(acc1[2], b1d[2]));
            float2 ov = unpk(padd(acc1[3], b1d[3]));
            c1x = sigm(fv.x) * c1x + sigm(iv.x) * tanh_(gv.x);
            c1y = sigm(fv.y) * c1y + sigm(iv.y) * tanh_(gv.y);
            __stcg((float2*)(g_h1[(t + 1) & 1] + (size_t)u * BB + aofs),
                   make_float2(sigm(ov.x) * tanh_(c1x), sigm(ov.y) * tanh_(c1y)));
        }
        if (t < TT) group_barrier(bb, ub, (unsigned)(t + 1));
    }
}

// ---------------- dense + softmax (final h1(1023) = g_h1[1]) ------------------------
__global__ __launch_bounds__(256) void dense_softmax(const float* __restrict__ Wd,
                                                     const float* __restrict__ bd,
                                                     float* __restrict__ out) {
    const int b = threadIdx.x;
    const float* h = g_h1[1];
    float acc[CC];
#pragma unroll
    for (int c = 0; c < CC; ++c) acc[c] = bd[c];
    for (int u = 0; u < HH; ++u) {
        float hv = h[(size_t)u * BB + b];
#pragma unroll
        for (int c = 0; c < CC; ++c) acc[c] += hv * Wd[c * HH + u];
    }
    float mx = acc[0];
#pragma unroll
    for (int c = 1; c < CC; ++c) mx = fmaxf(mx, acc[c]);
    float sum = 0.f;
#pragma unroll
    for (int c = 0; c < CC; ++c) { acc[c] = expf(acc[c] - mx); sum += acc[c]; }
    float inv = 1.f / sum;
#pragma unroll
    for (int c = 0; c < CC; ++c) out[b * CC + c] = acc[c] * inv;
}

// ---------------- launch --------------------------------------------------------------
extern "C" void kernel_launch(void* const* d_in, const int* in_sizes, int n_in,
                              void* d_out, int out_size) {
    const float* x    = (const float*)d_in[0];
    const float* Wih0 = (const float*)d_in[1];
    const float* Whh0 = (const float*)d_in[2];
    const float* b0v  = (const float*)d_in[3];
    const float* Wih1 = (const float*)d_in[4];
    const float* Whh1 = (const float*)d_in[5];
    const float* b1v  = (const float*)d_in[6];
    const float* Wd   = (const float*)d_in[7];
    const float* bd   = (const float*)d_in[8];
    float* out = (float*)d_out;

    cudaFuncSetAttribute(lstm_persist, cudaFuncAttributeMaxDynamicSharedMemorySize, SMEM_BYTES);

    const int NW = DD * HH * 4 + 3 * HH * HH * 4;
    const int tw_blocks = (NW + 255) / 256;

    init_kernel<<<64, 256>>>();                                         // 0
    prep_kernel<<<4096 + tw_blocks, 256>>>(x, Wih0, Whh0, Wih1, Whh1);  // 1
    xg0_kernel<<<TT * 32, 128>>>(b0v);                                  // 2
    lstm_persist<<<NBLK, NTHR, SMEM_BYTES>>>(b1v);                      // 3
    dense_softmax<<<1, 256>>>(Wd, bd, out);                             // 4
}

// round 10
// speedup vs baseline: 2.4952x; 1.2757x over previous
#include <cuda_runtime.h>

#define BB 256
#define TT 1024
#define DD 128
#define HH 256
#define CC 10
#define NBLK 128     // 32 unit-blocks x 4 batch-groups
#define NTHR 256

typedef unsigned long long u64;

// ---------------- device scratch ------------------------------------------------
__device__ float g_xT [(size_t)TT * DD * BB];        // [t][d][b]
__device__ float g_xg0[(size_t)TT * HH * BB * 4];    // [t][u][b][g]
__device__ float g_h0[2][HH * BB];                   // h0(t) in slot t&1
__device__ float g_h1[2][HH * BB];                   // h1(s) in slot s&1
__device__ float g_Wt_ih0[DD * HH * 4];              // [k][u][g]
__device__ float g_Wt_hh0[HH * HH * 4];
__device__ float g_Wt_ih1[HH * HH * 4];
__device__ float g_Wt_hh1[HH * HH * 4];
__device__ unsigned g_flags[4][32];                  // [batch-group][unit-block]
__device__ unsigned g_rel[4];

// ---------------- packed fp32x2 helpers ------------------------------------------
__device__ __forceinline__ u64 dup2(float w) {
    u64 r; asm("mov.b64 %0,{%1,%1};" : "=l"(r) : "f"(w)); return r;
}
__device__ __forceinline__ u64 pk2(float lo, float hi) {
    u64 r; asm("mov.b64 %0,{%1,%2};" : "=l"(r) : "f"(lo), "f"(hi)); return r;
}
__device__ __forceinline__ void pfma(u64& d, u64 a, u64 b) {
    asm("fma.rn.f32x2 %0,%1,%2,%0;" : "+l"(d) : "l"(a), "l"(b));
}
__device__ __forceinline__ u64 padd(u64 a, u64 b) {
    u64 r; asm("add.rn.f32x2 %0,%1,%2;" : "=l"(r) : "l"(a), "l"(b)); return r;
}
__device__ __forceinline__ float2 unpk(u64 v) {
    float2 f; asm("mov.b64 {%0,%1},%2;" : "=f"(f.x), "=f"(f.y) : "l"(v)); return f;
}
__device__ __forceinline__ float sigm(float x) { return 1.f / (1.f + __expf(-x)); }
__device__ __forceinline__ float tanh_(float x) { return 1.f - 2.f / (__expf(2.f * x) + 1.f); }

__device__ __forceinline__ void cpa16(void* smem_dst, const void* gsrc) {
    unsigned su = (unsigned)__cvta_generic_to_shared(smem_dst);
    asm volatile("cp.async.cg.shared.global [%0], [%1], 16;" :: "r"(su), "l"(gsrc) : "memory");
}
__device__ __forceinline__ void cpa_commit() {
    asm volatile("cp.async.commit_group;" ::: "memory");
}

// ---------------- init (every replay) ---------------------------------------------
__global__ void init_kernel() {
    int n = HH * BB;
    for (int i = blockIdx.x * blockDim.x + threadIdx.x; i < n; i += gridDim.x * blockDim.x) {
        g_h0[1][i] = 0.f;   // h0(-1)
        g_h1[1][i] = 0.f;   // h1(-1)
        g_h1[0][i] = 0.f;   // staged-but-unused source at t=0; keep deterministic
    }
    int idx = blockIdx.x * blockDim.x + threadIdx.x;
    if (idx < 128) g_flags[idx >> 5][idx & 31] = 0u;
    if (idx < 4) g_rel[idx] = 0u;
}

// ---------------- prep: x transpose + weight transpose ----------------------------
__global__ __launch_bounds__(256) void prep_kernel(const float* __restrict__ x,
                                                   const float* __restrict__ Wih0,
                                                   const float* __restrict__ Whh0,
                                                   const float* __restrict__ Wih1,
                                                   const float* __restrict__ Whh1) {
    const int bid = blockIdx.x;
    if (bid < 4096) {
        __shared__ float tile[64][33];
        const int t = bid >> 2, b0 = (bid & 3) * 64;
        for (int dc = 0; dc < DD; dc += 32) {
            for (int i = threadIdx.x; i < 64 * 32; i += 256) {
                int bi = i >> 5, di = i & 31;
                tile[bi][di] = x[((size_t)(b0 + bi) * TT + t) * DD + dc + di];
            }
            __syncthreads();
            for (int i = threadIdx.x; i < 64 * 32; i += 256) {
                int di = i >> 6, bi = i & 63;
                g_xT[((size_t)t * DD + dc + di) * BB + b0 + bi] = tile[bi][di];
            }
            __syncthreads();
        }
    } else {
        const int NI = DD * HH * 4, NH = HH * HH * 4;
        int idx = (bid - 4096) * 256 + threadIdx.x;
        if (idx < NI) {
            int g = idx & 3, u = (idx >> 2) & 255, k = idx >> 10;
            g_Wt_ih0[idx] = Wih0[(g * HH + u) * DD + k];
        } else if (idx < NI + 3 * NH) {
            int j = idx - NI, m = j / NH, r = j % NH;
            int g = r & 3, u = (r >> 2) & 255, k = r >> 10;
            if (m == 0)      g_Wt_hh0[r] = Whh0[(g * HH + u) * HH + k];
            else if (m == 1) g_Wt_ih1[r] = Wih1[(g * HH + u) * HH + k];
            else             g_Wt_hh1[r] = Whh1[(g * HH + u) * HH + k];
        }
    }
}

// ---------------- xg0 = x @ Wih0^T + b0, layout [t][u][b][g] -----------------------
__device__ __forceinline__ void gemm_2u(const float* __restrict__ A,
                                        const float* __restrict__ Wt,
                                        int K, int bofs, int u0, u64 acc[2][4][4]) {
#pragma unroll 2
    for (int k = 0; k < K; ++k) {
        ulonglong2 a0 = *(const ulonglong2*)(A + (size_t)k * BB + bofs);
        ulonglong2 a1 = *(const ulonglong2*)(A + (size_t)k * BB + bofs + 4);
        float4 w0 = *(const float4*)(Wt + ((size_t)k * HH + u0) * 4);
        float4 w1 = *(const float4*)(Wt + ((size_t)k * HH + u0 + 1) * 4);
        u64 a[4] = {a0.x, a0.y, a1.x, a1.y};
        float wv0[4] = {w0.x, w0.y, w0.z, w0.w};
        float wv1[4] = {w1.x, w1.y, w1.z, w1.w};
#pragma unroll
        for (int g = 0; g < 4; ++g) {
            u64 wp = dup2(wv0[g]);
#pragma unroll
            for (int p = 0; p < 4; ++p) pfma(acc[0][g][p], a[p], wp);
        }
#pragma unroll
        for (int g = 0; g < 4; ++g) {
            u64 wp = dup2(wv1[g]);
#pragma unroll
            for (int p = 0; p < 4; ++p) pfma(acc[1][g][p], a[p], wp);
        }
    }
}

__global__ __launch_bounds__(128) void xg0_kernel(const float* __restrict__ b0v) {
    const int bid = blockIdx.x;
    const int t = bid >> 5, sub = bid & 31;
    const int ub = sub >> 2, bb = sub & 3;
    const int m_t = threadIdx.x & 7, n_t = threadIdx.x >> 3;
    const int u0 = ub * 32 + n_t * 2;
    const int bofs = bb * 64 + m_t * 8;

    u64 acc[2][4][4];
#pragma unroll
    for (int uu = 0; uu < 2; ++uu)
#pragma unroll
        for (int g = 0; g < 4; ++g) {
            u64 bp = dup2(b0v[g * HH + u0 + uu]);
#pragma unroll
            for (int p = 0; p < 4; ++p) acc[uu][g][p] = bp;
        }
    gemm_2u(g_xT + (size_t)t * DD * BB, g_Wt_ih0, DD, bofs, u0, acc);

    float* X = g_xg0 + (size_t)t * HH * BB * 4;
#pragma unroll
    for (int uu = 0; uu < 2; ++uu)
#pragma unroll
        for (int p = 0; p < 4; ++p) {
            float2 gi = unpk(acc[uu][0][p]);
            float2 gf = unpk(acc[uu][1][p]);
            float2 gg = unpk(acc[uu][2][p]);
            float2 go = unpk(acc[uu][3][p]);
            float* dst = X + ((size_t)(u0 + uu) * BB + bofs + p * 2) * 4;
            *(float4*)dst       = make_float4(gi.x, gf.x, gg.x, go.x);  // batch b0: i f g o
            *(float4*)(dst + 4) = make_float4(gi.y, gf.y, gg.y, go.y);  // batch b1
        }
}

// ---------------- grouped grid barrier (4 independent groups of 32 blocks) ---------
__device__ __forceinline__ void group_barrier(int bb, int ub, unsigned gen) {
    __threadfence();
    __syncthreads();
    if (threadIdx.x == 0) *(volatile unsigned*)&g_flags[bb][ub] = gen;
    if (ub == 0 && threadIdx.x < 32) {
        while (*(volatile unsigned*)&g_flags[bb][threadIdx.x] < gen) __nanosleep(20);
        __syncwarp();
        if (threadIdx.x == 0) {
            __threadfence();
            *(volatile unsigned*)&g_rel[bb] = gen;
        }
    }
    if (threadIdx.x == 0) {
        while (*(volatile unsigned*)&g_rel[bb] < gen) __nanosleep(20);
        __threadfence();
    }
    __syncthreads();
}

// ---------------- persistent LSTM ---------------------------------------------------
// smem: non-dup weights 3 x 8192 f32 (96KB) + a-ring 4 x (32k x 64b) f32 (32KB) = 128KB
#define SW_F32     (3 * 8192)
#define RING_F32   (4 * 2048)
#define SMEM_BYTES ((SW_F32 + RING_F32) * 4)

// stage one 8KB chunk (32 k-rows x 64 floats) via cp.async
__device__ __forceinline__ void stage_chunk(float* buf, const float* src, int tid) {
    int s0 = tid * 2, s1 = s0 + 1;
    cpa16(buf + (s0 >> 4) * 64 + (s0 & 15) * 4, src + (size_t)(s0 >> 4) * BB + (s0 & 15) * 4);
    cpa16(buf + (s1 >> 4) * 64 + (s1 & 15) * 4, src + (size_t)(s1 >> 4) * BB + (s1 & 15) * 4);
    cpa_commit();
}

__global__ __launch_bounds__(NTHR, 1) void lstm_persist(const float* __restrict__ b1v) {
    extern __shared__ float smemf[];
    float* sw0  = smemf;                 // hh0: [chunk][kk][uloc][g] f32, 8192
    float* sw1  = smemf + 8192;          // ih1
    float* sw2  = smemf + 16384;         // hh1
    float* ring = smemf + SW_F32;        // 4 x 2048

    const int tid  = threadIdx.x;
    const int warp = tid >> 5, lane = tid & 31;
    const int pl = lane & 15, ul = lane >> 4;
    const int pg = warp & 1,  ug = warp >> 1;
    const int pair = pg * 16 + pl;         // 0..31 (batch pair within 64-b group)
    const int uloc = ug * 2 + ul;          // 0..7
    const int ub = blockIdx.x >> 2, bb = blockIdx.x & 3;
    const int u = ub * 8 + uloc;
    const int bbase = bb * 64;
    const int aofs = bbase + pair * 2;

    // one-time non-duplicated weight load: sw[(k*8+uloc)*4+g] = W[k][ub*8+uloc][g]
    {
        const float* srcs[3] = {g_Wt_hh0, g_Wt_ih1, g_Wt_hh1};
        float* dsts[3] = {sw0, sw1, sw2};
#pragma unroll
        for (int m = 0; m < 3; ++m) {
            const float* src = srcs[m] + ub * 32;
            float* dst = dsts[m];
            for (int idx = tid; idx < 8192; idx += NTHR)
                dst[idx] = src[(size_t)(idx >> 5) * 1024 + (idx & 31)];
        }
    }
    // L1 biases as gate-pairs: {i,f} and {g,o}
    u64 b1d[2];
    b1d[0] = pk2(b1v[0 * HH + u], b1v[1 * HH + u]);
    b1d[1] = pk2(b1v[2 * HH + u], b1v[3 * HH + u]);

    float c0[2] = {0.f, 0.f}, c1[2] = {0.f, 0.f};
    __syncthreads();

    for (int t = 0; t <= TT; ++t) {
        const float* h0p  = g_h0[(t + 1) & 1] + bbase;   // h0(t-1)
        const float* h1p2 = g_h1[t & 1]       + bbase;   // h1(t-2)

        // prefetch xg(t) as gate-pairs (layout [u][b][g], LDG.128 per batch)
        u64 xgr[2][2];
        if (t < TT) {
            const float* xg = g_xg0 + (((size_t)t * HH + u) * BB + aofs) * 4;
            float4 x0 = __ldcg((const float4*)xg);
            float4 x1 = __ldcg((const float4*)(xg + 4));
            xgr[0][0] = pk2(x0.x, x0.y); xgr[0][1] = pk2(x0.z, x0.w);
            xgr[1][0] = pk2(x1.x, x1.y); xgr[1][1] = pk2(x1.z, x1.w);
        }

        // prologue: 2 chunks in flight (4-deep ring, distance 2 -> no WAR hazard)
        stage_chunk(ring,        h0p, tid);
        stage_chunk(ring + 2048, h0p + 32 * BB, tid);

        u64 acc0[2][2] = {{0, 0}, {0, 0}};   // [batch][gate-pair] for L0
        u64 acc1[2][2] = {{0, 0}, {0, 0}};   // for L1

        for (int c = 0; c < 16; ++c) {
            if (c + 2 < 16) {
                const float* nsrc = (c + 2 < 8) ? (h0p + (size_t)(c + 2) * 32 * BB)
                                                : (h1p2 + (size_t)(c - 6) * 32 * BB);
                stage_chunk(ring + ((c + 2) & 3) * 2048, nsrc, tid);
                asm volatile("cp.async.wait_group 2;" ::: "memory");
            } else if (c + 1 < 16) {
                asm volatile("cp.async.wait_group 1;" ::: "memory");
            } else {
                asm volatile("cp.async.wait_group 0;" ::: "memory");
            }
            __syncthreads();
            const float* bf = ring + (c & 3) * 2048;
            if (c < 8) {
                const float* w0b = sw0 + (size_t)c * 1024;
                const float* w1b = sw1 + (size_t)c * 1024;
#pragma unroll 8
                for (int kk = 0; kk < 32; ++kk) {
                    float2 av = *(const float2*)(bf + kk * 64 + pair * 2);
                    u64 a0 = dup2(av.x), a1 = dup2(av.y);
                    ulonglong2 wA = *(const ulonglong2*)(w0b + kk * 32 + uloc * 4);
                    ulonglong2 wB = *(const ulonglong2*)(w1b + kk * 32 + uloc * 4);
                    pfma(acc0[0][0], a0, wA.x); pfma(acc0[0][1], a0, wA.y);
                    pfma(acc0[1][0], a1, wA.x); pfma(acc0[1][1], a1, wA.y);
                    pfma(acc1[0][0], a0, wB.x); pfma(acc1[0][1], a0, wB.y);
                    pfma(acc1[1][0], a1, wB.x); pfma(acc1[1][1], a1, wB.y);
                }
            } else {
                const float* w2b = sw2 + (size_t)(c - 8) * 1024;
#pragma unroll 8
                for (int kk = 0; kk < 32; ++kk) {
                    float2 av = *(const float2*)(bf + kk * 64 + pair * 2);
                    u64 a0 = dup2(av.x), a1 = dup2(av.y);
                    ulonglong2 wA = *(const ulonglong2*)(w2b + kk * 32 + uloc * 4);
                    pfma(acc1[0][0], a0, wA.x); pfma(acc1[0][1], a0, wA.y);
                    pfma(acc1[1][0], a1, wA.x); pfma(acc1[1][1], a1, wA.y);
                }
            }
        }

        // pointwise L0: h0(t)
        if (t < TT) {
            float hv[2];
#pragma unroll
            for (int b = 0; b < 2; ++b) {
                float2 if_ = unpk(padd(acc0[b][0], xgr[b][0]));
                float2 go  = unpk(padd(acc0[b][1], xgr[b][1]));
                c0[b] = sigm(if_.y) * c0[b] + sigm(if_.x) * tanh_(go.x);
                hv[b] = sigm(go.y) * tanh_(c0[b]);
            }
            __stcg((float2*)(g_h0[t & 1] + (size_t)u * BB + aofs), make_float2(hv[0], hv[1]));
        }
        // pointwise L1: h1(t-1)
        if (t >= 1) {
            float hv[2];
#pragma unroll
            for (int b = 0; b < 2; ++b) {
                float2 if_ = unpk(padd(acc1[b][0], b1d[0]));
                float2 go  = unpk(padd(acc1[b][1], b1d[1]));
                c1[b] = sigm(if_.y) * c1[b] + sigm(if_.x) * tanh_(go.x);
                hv[b] = sigm(go.y) * tanh_(c1[b]);
            }
            __stcg((float2*)(g_h1[(t + 1) & 1] + (size_t)u * BB + aofs), make_float2(hv[0], hv[1]));
        }
        if (t < TT) group_barrier(bb, ub, (unsigned)(t + 1));
    }
}

// ---------------- dense + softmax (final h1(1023) = g_h1[1]) ------------------------
__global__ __launch_bounds__(256) void dense_softmax(const float* __restrict__ Wd,
                                                     const float* __restrict__ bd,
                                                     float* __restrict__ out) {
    const int b = threadIdx.x;
    const float* h = g_h1[1];
    float acc[CC];
#pragma unroll
    for (int c = 0; c < CC; ++c) acc[c] = bd[c];
    for (int u = 0; u < HH; ++u) {
        float hv = h[(size_t)u * BB + b];
#pragma unroll
        for (int c = 0; c < CC; ++c) acc[c] += hv * Wd[c * HH + u];
    }
    float mx = acc[0];
#pragma unroll
    for (int c = 1; c < CC; ++c) mx = fmaxf(mx, acc[c]);
    float sum = 0.f;
#pragma unroll
    for (int c = 0; c < CC; ++c) { acc[c] = expf(acc[c] - mx); sum += acc[c]; }
    float inv = 1.f / sum;
#pragma unroll
    for (int c = 0; c < CC; ++c) out[b * CC + c] = acc[c] * inv;
}

// ---------------- launch --------------------------------------------------------------
extern "C" void kernel_launch(void* const* d_in, const int* in_sizes, int n_in,
                              void* d_out, int out_size) {
    const float* x    = (const float*)d_in[0];
    const float* Wih0 = (const float*)d_in[1];
    const float* Whh0 = (const float*)d_in[2];
    const float* b0v  = (const float*)d_in[3];
    const float* Wih1 = (const float*)d_in[4];
    const float* Whh1 = (const float*)d_in[5];
    const float* b1v  = (const float*)d_in[6];
    const float* Wd   = (const float*)d_in[7];
    const float* bd   = (const float*)d_in[8];
    float* out = (float*)d_out;

    cudaFuncSetAttribute(lstm_persist, cudaFuncAttributeMaxDynamicSharedMemorySize, SMEM_BYTES);

    const int NW = DD * HH * 4 + 3 * HH * HH * 4;
    const int tw_blocks = (NW + 255) / 256;

    init_kernel<<<64, 256>>>();                                         // 0
    prep_kernel<<<4096 + tw_blocks, 256>>>(x, Wih0, Whh0, Wih1, Whh1);  // 1
    xg0_kernel<<<TT * 32, 128>>>(b0v);                                  // 2
    lstm_persist<<<NBLK, NTHR, SMEM_BYTES>>>(b1v);                      // 3
    dense_softmax<<<1, 256>>>(Wd, bd, out);                             // 4
}

// round 11
// speedup vs baseline: 2.5117x; 1.0066x over previous
#include <cuda_runtime.h>

#define BB 256
#define TT 1024
#define DD 128
#define HH 256
#define CC 10
#define NBLK 128     // 32 unit-blocks x 4 batch-groups
#define NTHR 256

typedef unsigned long long u64;

// ---------------- device scratch ------------------------------------------------
__device__ float g_xT [(size_t)TT * DD * BB];        // [t][d][b]
__device__ float g_xg0[(size_t)TT * HH * BB * 4];    // [t][u][b][g]
__device__ float g_h0[2][HH * BB];                   // h0(t) in slot t&1
__device__ float g_h1[2][HH * BB];                   // h1(s) in slot s&1
__device__ float g_Wt_ih0[DD * HH * 4];              // [k][u][g]
__device__ float g_Wt_hh0[HH * HH * 4];
__device__ float g_Wt_ih1[HH * HH * 4];
__device__ float g_Wt_hh1[HH * HH * 4];
__device__ unsigned g_flags[4][32];                  // [batch-group][unit-block]
__device__ unsigned g_rel[4];

// ---------------- packed fp32x2 helpers ------------------------------------------
__device__ __forceinline__ u64 dup2(float w) {
    u64 r; asm("mov.b64 %0,{%1,%1};" : "=l"(r) : "f"(w)); return r;
}
__device__ __forceinline__ u64 pk2(float lo, float hi) {
    u64 r; asm("mov.b64 %0,{%1,%2};" : "=l"(r) : "f"(lo), "f"(hi)); return r;
}
__device__ __forceinline__ void pfma(u64& d, u64 a, u64 b) {
    asm("fma.rn.f32x2 %0,%1,%2,%0;" : "+l"(d) : "l"(a), "l"(b));
}
__device__ __forceinline__ u64 padd(u64 a, u64 b) {
    u64 r; asm("add.rn.f32x2 %0,%1,%2;" : "=l"(r) : "l"(a), "l"(b)); return r;
}
__device__ __forceinline__ float2 unpk(u64 v) {
    float2 f; asm("mov.b64 {%0,%1},%2;" : "=f"(f.x), "=f"(f.y) : "l"(v)); return f;
}
__device__ __forceinline__ float sigm(float x) { return 1.f / (1.f + __expf(-x)); }
__device__ __forceinline__ float tanh_(float x) { return 1.f - 2.f / (__expf(2.f * x) + 1.f); }

__device__ __forceinline__ void cpa16(void* smem_dst, const void* gsrc) {
    unsigned su = (unsigned)__cvta_generic_to_shared(smem_dst);
    asm volatile("cp.async.cg.shared.global [%0], [%1], 16;" :: "r"(su), "l"(gsrc) : "memory");
}
__device__ __forceinline__ void cpa_commit() {
    asm volatile("cp.async.commit_group;" ::: "memory");
}

// ---------------- init (every replay) ---------------------------------------------
__global__ void init_kernel() {
    int n = HH * BB;
    for (int i = blockIdx.x * blockDim.x + threadIdx.x; i < n; i += gridDim.x * blockDim.x) {
        g_h0[1][i] = 0.f;   // h0(-1)
        g_h1[1][i] = 0.f;   // h1(-1)
        g_h1[0][i] = 0.f;   // staged-but-unused source at t=0; keep deterministic
    }
    int idx = blockIdx.x * blockDim.x + threadIdx.x;
    if (idx < 128) g_flags[idx >> 5][idx & 31] = 0u;
    if (idx < 4) g_rel[idx] = 0u;
}

// ---------------- prep: x transpose + weight transpose ----------------------------
__global__ __launch_bounds__(256) void prep_kernel(const float* __restrict__ x,
                                                   const float* __restrict__ Wih0,
                                                   const float* __restrict__ Whh0,
                                                   const float* __restrict__ Wih1,
                                                   const float* __restrict__ Whh1) {
    const int bid = blockIdx.x;
    if (bid < 4096) {
        __shared__ float tile[64][33];
        const int t = bid >> 2, b0 = (bid & 3) * 64;
        for (int dc = 0; dc < DD; dc += 32) {
            for (int i = threadIdx.x; i < 64 * 32; i += 256) {
                int bi = i >> 5, di = i & 31;
                tile[bi][di] = x[((size_t)(b0 + bi) * TT + t) * DD + dc + di];
            }
            __syncthreads();
            for (int i = threadIdx.x; i < 64 * 32; i += 256) {
                int di = i >> 6, bi = i & 63;
                g_xT[((size_t)t * DD + dc + di) * BB + b0 + bi] = tile[bi][di];
            }
            __syncthreads();
        }
    } else {
        const int NI = DD * HH * 4, NH = HH * HH * 4;
        int idx = (bid - 4096) * 256 + threadIdx.x;
        if (idx < NI) {
            int g = idx & 3, u = (idx >> 2) & 255, k = idx >> 10;
            g_Wt_ih0[idx] = Wih0[(g * HH + u) * DD + k];
        } else if (idx < NI + 3 * NH) {
            int j = idx - NI, m = j / NH, r = j % NH;
            int g = r & 3, u = (r >> 2) & 255, k = r >> 10;
            if (m == 0)      g_Wt_hh0[r] = Whh0[(g * HH + u) * HH + k];
            else if (m == 1) g_Wt_ih1[r] = Wih1[(g * HH + u) * HH + k];
            else             g_Wt_hh1[r] = Whh1[(g * HH + u) * HH + k];
        }
    }
}

// ---------------- xg0 = x @ Wih0^T + b0, layout [t][u][b][g] -----------------------
__device__ __forceinline__ void gemm_2u(const float* __restrict__ A,
                                        const float* __restrict__ Wt,
                                        int K, int bofs, int u0, u64 acc[2][4][4]) {
#pragma unroll 2
    for (int k = 0; k < K; ++k) {
        ulonglong2 a0 = *(const ulonglong2*)(A + (size_t)k * BB + bofs);
        ulonglong2 a1 = *(const ulonglong2*)(A + (size_t)k * BB + bofs + 4);
        float4 w0 = *(const float4*)(Wt + ((size_t)k * HH + u0) * 4);
        float4 w1 = *(const float4*)(Wt + ((size_t)k * HH + u0 + 1) * 4);
        u64 a[4] = {a0.x, a0.y, a1.x, a1.y};
        float wv0[4] = {w0.x, w0.y, w0.z, w0.w};
        float wv1[4] = {w1.x, w1.y, w1.z, w1.w};
#pragma unroll
        for (int g = 0; g < 4; ++g) {
            u64 wp = dup2(wv0[g]);
#pragma unroll
            for (int p = 0; p < 4; ++p) pfma(acc[0][g][p], a[p], wp);
        }
#pragma unroll
        for (int g = 0; g < 4; ++g) {
            u64 wp = dup2(wv1[g]);
#pragma unroll
            for (int p = 0; p < 4; ++p) pfma(acc[1][g][p], a[p], wp);
        }
    }
}

__global__ __launch_bounds__(128) void xg0_kernel(const float* __restrict__ b0v) {
    const int bid = blockIdx.x;
    const int t = bid >> 5, sub = bid & 31;
    const int ub = sub >> 2, bb = sub & 3;
    const int m_t = threadIdx.x & 7, n_t = threadIdx.x >> 3;
    const int u0 = ub * 32 + n_t * 2;
    const int bofs = bb * 64 + m_t * 8;

    u64 acc[2][4][4];
#pragma unroll
    for (int uu = 0; uu < 2; ++uu)
#pragma unroll
        for (int g = 0; g < 4; ++g) {
            u64 bp = dup2(b0v[g * HH + u0 + uu]);
#pragma unroll
            for (int p = 0; p < 4; ++p) acc[uu][g][p] = bp;
        }
    gemm_2u(g_xT + (size_t)t * DD * BB, g_Wt_ih0, DD, bofs, u0, acc);

    float* X = g_xg0 + (size_t)t * HH * BB * 4;
#pragma unroll
    for (int uu = 0; uu < 2; ++uu)
#pragma unroll
        for (int p = 0; p < 4; ++p) {
            float2 gi = unpk(acc[uu][0][p]);
            float2 gf = unpk(acc[uu][1][p]);
            float2 gg = unpk(acc[uu][2][p]);
            float2 go = unpk(acc[uu][3][p]);
            float* dst = X + ((size_t)(u0 + uu) * BB + bofs + p * 2) * 4;
            *(float4*)dst       = make_float4(gi.x, gf.x, gg.x, go.x);  // batch b0: i f g o
            *(float4*)(dst + 4) = make_float4(gi.y, gf.y, gg.y, go.y);  // batch b1
        }
}

// ---------------- grouped grid barrier (4 independent groups of 32 blocks) ---------
__device__ __forceinline__ void group_barrier(int bb, int ub, unsigned gen) {
    __threadfence();
    __syncthreads();
    if (threadIdx.x == 0) *(volatile unsigned*)&g_flags[bb][ub] = gen;
    if (ub == 0 && threadIdx.x < 32) {
        while (*(volatile unsigned*)&g_flags[bb][threadIdx.x] < gen) __nanosleep(20);
        __syncwarp();
        if (threadIdx.x == 0) {
            __threadfence();
            *(volatile unsigned*)&g_rel[bb] = gen;
        }
    }
    if (threadIdx.x == 0) {
        while (*(volatile unsigned*)&g_rel[bb] < gen) __nanosleep(20);
        __threadfence();
    }
    __syncthreads();
}

// ---------------- persistent LSTM ---------------------------------------------------
// smem: non-dup weights 3 x 8192 f32 (96KB) + a-ring 4 x (32k x 64b) f32 (32KB) = 128KB
#define SW_F32     (3 * 8192)
#define RING_F32   (4 * 2048)
#define SMEM_BYTES ((SW_F32 + RING_F32) * 4)

// stage one 8KB chunk (32 k-rows x 64 floats) via cp.async
__device__ __forceinline__ void stage_chunk(float* buf, const float* src, int tid) {
    int s0 = tid * 2, s1 = s0 + 1;
    cpa16(buf + (s0 >> 4) * 64 + (s0 & 15) * 4, src + (size_t)(s0 >> 4) * BB + (s0 & 15) * 4);
    cpa16(buf + (s1 >> 4) * 64 + (s1 & 15) * 4, src + (size_t)(s1 >> 4) * BB + (s1 & 15) * 4);
    cpa_commit();
}

__global__ __launch_bounds__(NTHR, 1) void lstm_persist(const float* __restrict__ b1v) {
    extern __shared__ float smemf[];
    float* sw0  = smemf;                 // hh0: [chunk][kk][uloc][g] f32, 8192
    float* sw1  = smemf + 8192;          // ih1
    float* sw2  = smemf + 16384;         // hh1
    float* ring = smemf + SW_F32;        // 4 x 2048

    const int tid  = threadIdx.x;
    const int warp = tid >> 5, lane = tid & 31;
    const int pl = lane & 15, ul = lane >> 4;
    const int pg = warp & 1,  ug = warp >> 1;
    const int pair = pg * 16 + pl;         // 0..31 (batch pair within 64-b group)
    const int uloc = ug * 2 + ul;          // 0..7
    const int ub = blockIdx.x >> 2, bb = blockIdx.x & 3;
    const int u = ub * 8 + uloc;
    const int bbase = bb * 64;
    const int aofs = bbase + pair * 2;

    // one-time non-duplicated weight load: sw[(k*8+uloc)*4+g] = W[k][ub*8+uloc][g]
    {
        const float* srcs[3] = {g_Wt_hh0, g_Wt_ih1, g_Wt_hh1};
        float* dsts[3] = {sw0, sw1, sw2};
#pragma unroll
        for (int m = 0; m < 3; ++m) {
            const float* src = srcs[m] + ub * 32;
            float* dst = dsts[m];
            for (int idx = tid; idx < 8192; idx += NTHR)
                dst[idx] = src[(size_t)(idx >> 5) * 1024 + (idx & 31)];
        }
    }
    // L1 biases as gate-pairs: {i,f} and {g,o}
    u64 b1d[2];
    b1d[0] = pk2(b1v[0 * HH + u], b1v[1 * HH + u]);
    b1d[1] = pk2(b1v[2 * HH + u], b1v[3 * HH + u]);

    float c0[2] = {0.f, 0.f}, c1[2] = {0.f, 0.f};
    __syncthreads();

    for (int t = 0; t <= TT; ++t) {
        const float* h0p  = g_h0[(t + 1) & 1] + bbase;   // h0(t-1)
        const float* h1p2 = g_h1[t & 1]       + bbase;   // h1(t-2)

        // prefetch xg(t) as gate-pairs (layout [u][b][g], LDG.128 per batch)
        u64 xgr[2][2];
        if (t < TT) {
            const float* xg = g_xg0 + (((size_t)t * HH + u) * BB + aofs) * 4;
            float4 x0 = __ldcg((const float4*)xg);
            float4 x1 = __ldcg((const float4*)(xg + 4));
            xgr[0][0] = pk2(x0.x, x0.y); xgr[0][1] = pk2(x0.z, x0.w);
            xgr[1][0] = pk2(x1.x, x1.y); xgr[1][1] = pk2(x1.z, x1.w);
        }

        // prologue: 2 chunks in flight (4-deep ring, distance 2 -> no WAR hazard)
        stage_chunk(ring,        h0p, tid);
        stage_chunk(ring + 2048, h0p + 32 * BB, tid);

        u64 acc0[2][2] = {{0, 0}, {0, 0}};   // [batch][gate-pair] for L0
        u64 acc1[2][2] = {{0, 0}, {0, 0}};   // for L1

        for (int c = 0; c < 16; ++c) {
            if (c + 2 < 16) {
                const float* nsrc = (c + 2 < 8) ? (h0p + (size_t)(c + 2) * 32 * BB)
                                                : (h1p2 + (size_t)(c - 6) * 32 * BB);
                stage_chunk(ring + ((c + 2) & 3) * 2048, nsrc, tid);
                asm volatile("cp.async.wait_group 2;" ::: "memory");
            } else if (c + 1 < 16) {
                asm volatile("cp.async.wait_group 1;" ::: "memory");
            } else {
                asm volatile("cp.async.wait_group 0;" ::: "memory");
            }
            __syncthreads();
            const float* bf = ring + (c & 3) * 2048;
            if (c < 8) {
                const float* w0b = sw0 + (size_t)c * 1024;
                const float* w1b = sw1 + (size_t)c * 1024;
#pragma unroll 8
                for (int kk = 0; kk < 32; ++kk) {
                    float2 av = *(const float2*)(bf + kk * 64 + pair * 2);
                    u64 a0 = dup2(av.x), a1 = dup2(av.y);
                    ulonglong2 wA = *(const ulonglong2*)(w0b + kk * 32 + uloc * 4);
                    ulonglong2 wB = *(const ulonglong2*)(w1b + kk * 32 + uloc * 4);
                    pfma(acc0[0][0], a0, wA.x); pfma(acc0[0][1], a0, wA.y);
                    pfma(acc0[1][0], a1, wA.x); pfma(acc0[1][1], a1, wA.y);
                    pfma(acc1[0][0], a0, wB.x); pfma(acc1[0][1], a0, wB.y);
                    pfma(acc1[1][0], a1, wB.x); pfma(acc1[1][1], a1, wB.y);
                }
            } else {
                const float* w2b = sw2 + (size_t)(c - 8) * 1024;
#pragma unroll 8
                for (int kk = 0; kk < 32; ++kk) {
                    float2 av = *(const float2*)(bf + kk * 64 + pair * 2);
                    u64 a0 = dup2(av.x), a1 = dup2(av.y);
                    ulonglong2 wA = *(const ulonglong2*)(w2b + kk * 32 + uloc * 4);
                    pfma(acc1[0][0], a0, wA.x); pfma(acc1[0][1], a0, wA.y);
                    pfma(acc1[1][0], a1, wA.x); pfma(acc1[1][1], a1, wA.y);
                }
            }
        }

        // pointwise L0: h0(t)
        if (t < TT) {
            float hv[2];
#pragma unroll
            for (int b = 0; b < 2; ++b) {
                float2 if_ = unpk(padd(acc0[b][0], xgr[b][0]));
                float2 go  = unpk(padd(acc0[b][1], xgr[b][1]));
                c0[b] = sigm(if_.y) * c0[b] + sigm(if_.x) * tanh_(go.x);
                hv[b] = sigm(go.y) * tanh_(c0[b]);
            }
            __stcg((float2*)(g_h0[t & 1] + (size_t)u * BB + aofs), make_float2(hv[0], hv[1]));
        }
        // pointwise L1: h1(t-1)
        if (t >= 1) {
            float hv[2];
#pragma unroll
            for (int b = 0; b < 2; ++b) {
                float2 if_ = unpk(padd(acc1[b][0], b1d[0]));
                float2 go  = unpk(padd(acc1[b][1], b1d[1]));
                c1[b] = sigm(if_.y) * c1[b] + sigm(if_.x) * tanh_(go.x);
                hv[b] = sigm(go.y) * tanh_(c1[b]);
            }
            __stcg((float2*)(g_h1[(t + 1) & 1] + (size_t)u * BB + aofs), make_float2(hv[0], hv[1]));
        }
        if (t < TT) group_barrier(bb, ub, (unsigned)(t + 1));
    }
}

// ---------------- dense + softmax (final h1(1023) = g_h1[1]) ------------------------
__global__ __launch_bounds__(256) void dense_softmax(const float* __restrict__ Wd,
                                                     const float* __restrict__ bd,
                                                     float* __restrict__ out) {
    const int b = threadIdx.x;
    const float* h = g_h1[1];
    float acc[CC];
#pragma unroll
    for (int c = 0; c < CC; ++c) acc[c] = bd[c];
    for (int u = 0; u < HH; ++u) {
        float hv = h[(size_t)u * BB + b];
#pragma unroll
        for (int c = 0; c < CC; ++c) acc[c] += hv * Wd[c * HH + u];
    }
    float mx = acc[0];
#pragma unroll
    for (int c = 1; c < CC; ++c) mx = fmaxf(mx, acc[c]);
    float sum = 0.f;
#pragma unroll
    for (int c = 0; c < CC; ++c) { acc[c] = expf(acc[c] - mx); sum += acc[c]; }
    float inv = 1.f / sum;
#pragma unroll
    for (int c = 0; c < CC; ++c) out[b * CC + c] = acc[c] * inv;
}

// ---------------- launch --------------------------------------------------------------
extern "C" void kernel_launch(void* const* d_in, const int* in_sizes, int n_in,
                              void* d_out, int out_size) {
    const float* x    = (const float*)d_in[0];
    const float* Wih0 = (const float*)d_in[1];
    const float* Whh0 = (const float*)d_in[2];
    const float* b0v  = (const float*)d_in[3];
    const float* Wih1 = (const float*)d_in[4];
    const float* Whh1 = (const float*)d_in[5];
    const float* b1v  = (const float*)d_in[6];
    const float* Wd   = (const float*)d_in[7];
    const float* bd   = (const float*)d_in[8];
    float* out = (float*)d_out;

    cudaFuncSetAttribute(lstm_persist, cudaFuncAttributeMaxDynamicSharedMemorySize, SMEM_BYTES);

    const int NW = DD * HH * 4 + 3 * HH * HH * 4;
    const int tw_blocks = (NW + 255) / 256;

    init_kernel<<<64, 256>>>();                                         // 0
    prep_kernel<<<4096 + tw_blocks, 256>>>(x, Wih0, Whh0, Wih1, Whh1);  // 1
    xg0_kernel<<<TT * 32, 128>>>(b0v);                                  // 2
    lstm_persist<<<NBLK, NTHR, SMEM_BYTES>>>(b1v);                      // 3
    dense_softmax<<<1, 256>>>(Wd, bd, out);                             // 4
}